// round 8
// baseline (speedup 1.0000x reference)
#include <cuda_runtime.h>

// ---------------- problem constants ----------------
#define BB   2
#define TTT  2048
#define DM   512
#define NHD  8
#define DHD  64
#define NLAY 4
#define DI   2048
#define CIN  2048
#define NCLS 64
#define MR   (BB * TTT)   // 4096 token rows

// ---------------- scratch (device globals; no allocation allowed) ----------------
__device__ float g_xT[(size_t)BB * TTT * CIN];
__device__ float g_h[(size_t)MR * DM];
__device__ float g_tmp[(size_t)MR * DM];
__device__ float g_heads[(size_t)MR * 3 * DM];
__device__ float g_qw[(size_t)MR * DM];
__device__ float g_qr[(size_t)MR * DM];
__device__ float g_rk[(size_t)TTT * DM];
__device__ float g_pos[(size_t)TTT * DM];
__device__ float g_ff[(size_t)MR * DI];
__device__ float g_Bx[(size_t)BB * NHD * TTT * TTT];   // SHIFTED position scores (BDs layout)
__device__ float g_av[(size_t)MR * DM];
__device__ float g_cls[(size_t)MR * NCLS];
// pre-rounded (tf32) weights: emb | qkv | rproj | o | ff1 | ff2 | cls
#define W_EMB  0
#define W_QKV  (W_EMB + DM * CIN)                      // 1048576
#define W_RPJ  (W_QKV + NLAY * 3 * DM * DM)            // +3145728
#define W_O    (W_RPJ + NLAY * DM * DM)                // +1048576
#define W_FF1  (W_O + NLAY * DM * DM)                  // +1048576
#define W_FF2  (W_FF1 + NLAY * DI * DM)                // +4194304
#define W_CLS  (W_FF2 + NLAY * DM * DI)                // +4194304
#define W_END  (W_CLS + NCLS * DM)
__device__ float g_wbuf[(size_t)W_END];

// ---------------- tf32 / cp.async helpers ----------------
__device__ __forceinline__ unsigned f2tf(float x) {
    unsigned u;
    asm("cvt.rna.tf32.f32 %0, %1;" : "=r"(u) : "f"(x));
    return u;
}
__device__ __forceinline__ float f2tf_f(float x) { return __uint_as_float(f2tf(x)); }

__device__ __forceinline__ void mma_tf32(float* c, const unsigned* a, const unsigned* b) {
    asm volatile(
        "mma.sync.aligned.m16n8k8.row.col.f32.tf32.tf32.f32 "
        "{%0,%1,%2,%3}, {%4,%5,%6,%7}, {%8,%9}, {%0,%1,%2,%3};"
        : "+f"(c[0]), "+f"(c[1]), "+f"(c[2]), "+f"(c[3])
        : "r"(a[0]), "r"(a[1]), "r"(a[2]), "r"(a[3]), "r"(b[0]), "r"(b[1]));
}

__device__ __forceinline__ void cp16(void* dst, const void* src, int srcbytes) {
    unsigned u = (unsigned)__cvta_generic_to_shared(dst);
    asm volatile("cp.async.cg.shared.global [%0], [%1], 16, %2;"
                 :: "r"(u), "l"(src), "r"(srcbytes));
}
__device__ __forceinline__ void cp_commit() {
    asm volatile("cp.async.commit_group;");
}

// ---------------- pre-round weights to tf32 (bitwise in fp32 container) ----------------
__global__ void __launch_bounds__(256) round_copy(const float* __restrict__ src,
                                                 float* __restrict__ dst, int n)
{
    int i = (blockIdx.x * 256 + threadIdx.x) * 4;
    if (i < n) {
        float4 v = *(const float4*)(src + i);
        v.x = f2tf_f(v.x); v.y = f2tf_f(v.y); v.z = f2tf_f(v.z); v.w = f2tf_f(v.w);
        *(float4*)(dst + i) = v;
    }
}

// ---------------- TF32 tensor-core GEMM, 2-stage cp.async ----------------
// All operands PRE-ROUNDED to tf32 in gmem -> raw-bit fragments, paired-k float2 loads.
#define GSM_STAGE (128 * 36)
#define GEMM_SMEM (4 * GSM_STAGE * 4)   // 73728 B

__global__ void __launch_bounds__(256, 2) gemm_tf32(
    const float* __restrict__ A, int lda, size_t sAb, size_t sAn,
    const float* __restrict__ B, int ldb, size_t sBb, size_t sBn,
    const float* __restrict__ bias,
    float* __restrict__ C, int ldc, size_t sCb, size_t sCn,
    int M, int N, int K, int relu, int roundC,
    const float* __restrict__ rwb, const float* __restrict__ rrb,
    float* __restrict__ qwO, float* __restrict__ qrO)
{
    const int z = blockIdx.z, zb = z >> 3, zn = z & 7;
    A += (size_t)zb * sAb + (size_t)zn * sAn;
    B += (size_t)zb * sBb + (size_t)zn * sBn;
    C += (size_t)zb * sCb + (size_t)zn * sCn;

    extern __shared__ float gsm[];
    float* AsBase = gsm;
    float* BsBase = gsm + 2 * GSM_STAGE;

    const int tid = threadIdx.x;
    const int warp = tid >> 5, lane = tid & 31;
    const int wm = warp >> 2, wn = warp & 3;
    const int g = lane >> 2, tg = lane & 3;
    const int m0 = blockIdx.y * 128, n0 = blockIdx.x * 128;

    float acc[4][4][4];
#pragma unroll
    for (int mt = 0; mt < 4; mt++)
#pragma unroll
        for (int nt = 0; nt < 4; nt++)
#pragma unroll
            for (int i = 0; i < 4; i++) acc[mt][nt][i] = 0.f;

    const int KT = K >> 5;

    auto load_stage = [&](int st, int k0) {
#pragma unroll
        for (int i = 0; i < 4; i++) {
            int idx = tid + i * 256;
            int row = idx >> 3;
            int kq = (idx & 7) * 4;
            cp16(&AsBase[st * GSM_STAGE + row * 36 + kq],
                 A + (size_t)(m0 + row) * lda + k0 + kq, 16);
        }
#pragma unroll
        for (int i = 0; i < 4; i++) {
            int idx = tid + i * 256;
            int row = idx >> 3;
            int kq = (idx & 7) * 4;
            int ok = (n0 + row) < N;
            cp16(&BsBase[st * GSM_STAGE + row * 36 + kq],
                 B + (size_t)(ok ? (n0 + row) : 0) * ldb + k0 + kq, ok ? 16 : 0);
        }
        cp_commit();
    };

    load_stage(0, 0);

    for (int kt = 0; kt < KT; kt++) {
        const int st = kt & 1;
        if (kt + 1 < KT) {
            load_stage(st ^ 1, (kt + 1) * 32);
            asm volatile("cp.async.wait_group 1;");
        } else {
            asm volatile("cp.async.wait_group 0;");
        }
        __syncthreads();

        const float* Asl = AsBase + st * GSM_STAGE;
        const float* Bsl = BsBase + st * GSM_STAGE;

#pragma unroll
        for (int ks = 0; ks < 4; ks++) {
            const int kk = ks * 8 + 2 * tg;   // paired-k permutation {tg,tg+4}->{2tg,2tg+1}
            unsigned a[4][4], bb[4][2];
#pragma unroll
            for (int mt = 0; mt < 4; mt++) {
                int r = wm * 64 + mt * 16;
                float2 p0 = *(const float2*)(Asl + (r + g) * 36 + kk);
                float2 p1 = *(const float2*)(Asl + (r + g + 8) * 36 + kk);
                a[mt][0] = __float_as_uint(p0.x);
                a[mt][2] = __float_as_uint(p0.y);
                a[mt][1] = __float_as_uint(p1.x);
                a[mt][3] = __float_as_uint(p1.y);
            }
#pragma unroll
            for (int nt = 0; nt < 4; nt++) {
                int c = wn * 32 + nt * 8;
                float2 pb = *(const float2*)(Bsl + (c + g) * 36 + kk);
                bb[nt][0] = __float_as_uint(pb.x);
                bb[nt][1] = __float_as_uint(pb.y);
            }
#pragma unroll
            for (int mt = 0; mt < 4; mt++)
#pragma unroll
                for (int nt = 0; nt < 4; nt++)
                    mma_tf32(acc[mt][nt], a[mt], bb[nt]);
        }
        __syncthreads();
    }

#pragma unroll
    for (int mt = 0; mt < 4; mt++) {
        int r0 = m0 + wm * 64 + mt * 16 + g;
#pragma unroll
        for (int nt = 0; nt < 4; nt++) {
            int c0 = n0 + wn * 32 + nt * 8 + tg * 2;
            if (c0 < N) {
                float b0v = bias ? bias[c0] : 0.f;
                float b1v = bias ? bias[c0 + 1] : 0.f;
                float v0 = acc[mt][nt][0] + b0v;
                float v1 = acc[mt][nt][1] + b1v;
                float v2 = acc[mt][nt][2] + b0v;
                float v3 = acc[mt][nt][3] + b1v;
                if (relu) {
                    v0 = fmaxf(v0, 0.f); v1 = fmaxf(v1, 0.f);
                    v2 = fmaxf(v2, 0.f); v3 = fmaxf(v3, 0.f);
                }
                float s0 = v0, s1 = v1, s2 = v2, s3 = v3;
                if (roundC) {
                    s0 = f2tf_f(v0); s1 = f2tf_f(v1); s2 = f2tf_f(v2); s3 = f2tf_f(v3);
                }
                *(float2*)(C + (size_t)r0 * ldc + c0) = make_float2(s0, s1);
                *(float2*)(C + (size_t)(r0 + 8) * ldc + c0) = make_float2(s2, s3);
                if (qwO && c0 < DM) {
                    float w0 = rwb[c0], w1 = rwb[c0 + 1];
                    float r0b = rrb[c0], r1b = rrb[c0 + 1];
                    *(float2*)(qwO + (size_t)r0 * DM + c0) =
                        make_float2(f2tf_f(v0 + w0), f2tf_f(v1 + w1));
                    *(float2*)(qwO + (size_t)(r0 + 8) * DM + c0) =
                        make_float2(f2tf_f(v2 + w0), f2tf_f(v3 + w1));
                    *(float2*)(qrO + (size_t)r0 * DM + c0) =
                        make_float2(f2tf_f(v0 + r0b), f2tf_f(v1 + r1b));
                    *(float2*)(qrO + (size_t)(r0 + 8) * DM + c0) =
                        make_float2(f2tf_f(v2 + r0b), f2tf_f(v3 + r1b));
                }
            }
        }
    }
}

// ---------------- BD GEMM with shifted-scatter epilogue ----------------
__device__ __forceinline__ void bd_store(float* __restrict__ BDs, int i, int c, float v) {
    int thr = TTT - 1 - i;
    if (c >= thr)      BDs[(size_t)i * TTT + (c - thr)] = v;
    else if (i > 0)    BDs[(size_t)(i - 1) * TTT + (c + i + 1)] = v;
}

__global__ void __launch_bounds__(256, 2) gemm_bd(
    const float* __restrict__ A, int lda, size_t sAb, size_t sAn,   // qr (tf32-rounded)
    const float* __restrict__ B, int ldb, size_t sBn,               // rk (tf32-rounded)
    float* __restrict__ C, size_t sCbn)                             // BDs (fp32)
{
    const int z = blockIdx.z, zb = z >> 3, zn = z & 7;
    A += (size_t)zb * sAb + (size_t)zn * sAn;
    B += (size_t)zn * sBn;
    C += (size_t)z * sCbn;

    extern __shared__ float gsm[];
    float* AsBase = gsm;
    float* BsBase = gsm + 2 * GSM_STAGE;

    const int tid = threadIdx.x;
    const int warp = tid >> 5, lane = tid & 31;
    const int wm = warp >> 2, wn = warp & 3;
    const int g = lane >> 2, tg = lane & 3;
    const int m0 = blockIdx.y * 128, n0 = blockIdx.x * 128;

    float acc[4][4][4];
#pragma unroll
    for (int mt = 0; mt < 4; mt++)
#pragma unroll
        for (int nt = 0; nt < 4; nt++)
#pragma unroll
            for (int i = 0; i < 4; i++) acc[mt][nt][i] = 0.f;

    auto load_stage = [&](int st, int k0) {
#pragma unroll
        for (int i = 0; i < 4; i++) {
            int idx = tid + i * 256;
            int row = idx >> 3;
            int kq = (idx & 7) * 4;
            cp16(&AsBase[st * GSM_STAGE + row * 36 + kq],
                 A + (size_t)(m0 + row) * lda + k0 + kq, 16);
        }
#pragma unroll
        for (int i = 0; i < 4; i++) {
            int idx = tid + i * 256;
            int row = idx >> 3;
            int kq = (idx & 7) * 4;
            cp16(&BsBase[st * GSM_STAGE + row * 36 + kq],
                 B + (size_t)(n0 + row) * ldb + k0 + kq, 16);
        }
        cp_commit();
    };

    load_stage(0, 0);

#pragma unroll
    for (int kt = 0; kt < 2; kt++) {
        const int st = kt & 1;
        if (kt == 0) {
            load_stage(1, 32);
            asm volatile("cp.async.wait_group 1;");
        } else {
            asm volatile("cp.async.wait_group 0;");
        }
        __syncthreads();

        const float* Asl = AsBase + st * GSM_STAGE;
        const float* Bsl = BsBase + st * GSM_STAGE;

#pragma unroll
        for (int ks = 0; ks < 4; ks++) {
            const int kk = ks * 8 + 2 * tg;
            unsigned a[4][4], bb[4][2];
#pragma unroll
            for (int mt = 0; mt < 4; mt++) {
                int r = wm * 64 + mt * 16;
                float2 p0 = *(const float2*)(Asl + (r + g) * 36 + kk);
                float2 p1 = *(const float2*)(Asl + (r + g + 8) * 36 + kk);
                a[mt][0] = __float_as_uint(p0.x);
                a[mt][2] = __float_as_uint(p0.y);
                a[mt][1] = __float_as_uint(p1.x);
                a[mt][3] = __float_as_uint(p1.y);
            }
#pragma unroll
            for (int nt = 0; nt < 4; nt++) {
                int c = wn * 32 + nt * 8;
                float2 pb = *(const float2*)(Bsl + (c + g) * 36 + kk);
                bb[nt][0] = __float_as_uint(pb.x);
                bb[nt][1] = __float_as_uint(pb.y);
            }
#pragma unroll
            for (int mt = 0; mt < 4; mt++)
#pragma unroll
                for (int nt = 0; nt < 4; nt++)
                    mma_tf32(acc[mt][nt], a[mt], bb[nt]);
        }
        __syncthreads();
    }

#pragma unroll
    for (int mt = 0; mt < 4; mt++) {
        int i0r = m0 + wm * 64 + mt * 16 + g;
        int i1r = i0r + 8;
#pragma unroll
        for (int nt = 0; nt < 4; nt++) {
            int c0 = n0 + wn * 32 + nt * 8 + tg * 2;
            bd_store(C, i0r, c0,     acc[mt][nt][0]);
            bd_store(C, i0r, c0 + 1, acc[mt][nt][1]);
            bd_store(C, i1r, c0,     acc[mt][nt][2]);
            bd_store(C, i1r, c0 + 1, acc[mt][nt][3]);
        }
    }
}

// ---------------- fused flash attention (all MMA inputs pre-rounded) ----------------
#define SP_ELEMS (128 * 68)
#define SK_ELEMS (64 * 68)
#define SV_ELEMS (64 * 72)
#define FA_SMEM ((SP_ELEMS + 2 * SK_ELEMS + 2 * SV_ELEMS) * 4)

__global__ void __launch_bounds__(256, 1) flash_attn(
    const float* __restrict__ qw,     // [MR][512] tf32-rounded
    const float* __restrict__ heads,  // [MR][1536] tf32-rounded; K at +512, V at +1024
    const float* __restrict__ BDs,    // [16][T][T] pre-shifted fp32
    float* __restrict__ av,           // [MR][512]
    float scale)
{
    extern __shared__ unsigned smem_u[];
    unsigned* sP = smem_u;                                   // [128][68]
    float* sK = (float*)(smem_u + SP_ELEMS);                 // [2][64][68]
    float* sV = (float*)(smem_u + SP_ELEMS) + 2 * SK_ELEMS;  // [2][64][72]

    const int tid = threadIdx.x;
    const int w = tid >> 5, lane = tid & 31;
    const int g = lane >> 2, tg = lane & 3;
    const int i0 = blockIdx.x * 128;
    const int bn = blockIdx.y;
    const int b = bn >> 3, n = bn & 7;

    const float* Qb = qw + ((size_t)b * TTT) * DM + n * 64;
    const float* Kb = heads + DM + ((size_t)b * TTT) * (3 * DM) + n * 64;
    const float* Vb = heads + 2 * DM + ((size_t)b * TTT) * (3 * DM) + n * 64;
    const float* Bb = BDs + (size_t)bn * TTT * TTT;

    auto kv_load = [&](int st, int j0) {
#pragma unroll
        for (int it = 0; it < 4; it++) {
            int idx = tid + it * 256;
            int row = idx >> 4, c4 = (idx & 15) * 4;
            cp16(&sK[st * SK_ELEMS + row * 68 + c4],
                 Kb + (size_t)(j0 + row) * (3 * DM) + c4, 16);
        }
#pragma unroll
        for (int it = 0; it < 4; it++) {
            int idx = tid + it * 256;
            int row = idx >> 4, c4 = (idx & 15) * 4;
            cp16(&sV[st * SV_ELEMS + row * 72 + c4],
                 Vb + (size_t)(j0 + row) * (3 * DM) + c4, 16);
        }
        cp_commit();
    };

    kv_load(0, 0);

    // stage Q (already tf32-rounded -> raw bits)
#pragma unroll
    for (int it = 0; it < 8; it++) {
        int idx = tid + it * 256;
        int row = idx >> 4, c4 = (idx & 15) * 4;
        float4 v = *(const float4*)(Qb + (size_t)(i0 + row) * DM + c4);
        sP[row * 68 + c4 + 0] = __float_as_uint(v.x);
        sP[row * 68 + c4 + 1] = __float_as_uint(v.y);
        sP[row * 68 + c4 + 2] = __float_as_uint(v.z);
        sP[row * 68 + c4 + 3] = __float_as_uint(v.w);
    }
    __syncthreads();

    const int r0 = 16 * w + g;
    const int iR0 = i0 + r0, iR1 = iR0 + 8;
    const float* BDr0 = Bb + (size_t)iR0 * TTT;
    const float* BDr1 = Bb + (size_t)iR1 * TTT;

    unsigned qa[8][4];
#pragma unroll
    for (int kf = 0; kf < 8; kf++) {
        qa[kf][0] = sP[r0 * 68 + kf * 8 + tg];
        qa[kf][1] = sP[(r0 + 8) * 68 + kf * 8 + tg];
        qa[kf][2] = sP[r0 * 68 + kf * 8 + tg + 4];
        qa[kf][3] = sP[(r0 + 8) * 68 + kf * 8 + tg + 4];
    }

    float Oacc[8][4];
#pragma unroll
    for (int nf = 0; nf < 8; nf++)
#pragma unroll
        for (int i = 0; i < 4; i++) Oacc[nf][i] = 0.f;
    float mr0 = -1e30f, mr1 = -1e30f, lr0 = 0.f, lr1 = 0.f;

    for (int jt = 0; jt < TTT / 64; jt++) {
        const int st = jt & 1;
        const int j0 = jt * 64;
        if (jt + 1 < TTT / 64) {
            kv_load(st ^ 1, (jt + 1) * 64);
            asm volatile("cp.async.wait_group 1;");
        } else {
            asm volatile("cp.async.wait_group 0;");
        }
        __syncthreads();

        const float* Ks = sK + st * SK_ELEMS;
        const float* Vs = sV + st * SV_ELEMS;

        float2 y0v[8], y1v[8];
#pragma unroll
        for (int nf = 0; nf < 8; nf++) {
            int j = j0 + nf * 8 + 2 * tg;
            y0v[nf] = *(const float2*)(BDr0 + j);
            y1v[nf] = *(const float2*)(BDr1 + j);
        }

        // ---- S = Q @ K^T (raw bits; operands already tf32)
        float s[8][4];
#pragma unroll
        for (int nf = 0; nf < 8; nf++)
#pragma unroll
            for (int i = 0; i < 4; i++) s[nf][i] = 0.f;
#pragma unroll
        for (int kf = 0; kf < 8; kf++) {
            const int kk = kf * 8;
#pragma unroll
            for (int nf = 0; nf < 8; nf++) {
                unsigned bb[2];
                bb[0] = __float_as_uint(Ks[(nf * 8 + g) * 68 + kk + tg]);
                bb[1] = __float_as_uint(Ks[(nf * 8 + g) * 68 + kk + tg + 4]);
                mma_tf32(s[nf], qa[kf], bb);
            }
        }

#pragma unroll
        for (int nf = 0; nf < 8; nf++) {
            int j = j0 + nf * 8 + 2 * tg;
            float b00 = (j     == iR0 + 1) ? 0.f : y0v[nf].x;
            float b01 = (j + 1 == iR0 + 1) ? 0.f : y0v[nf].y;
            float b10 = (j     == iR1 + 1) ? 0.f : y1v[nf].x;
            float b11 = (j + 1 == iR1 + 1) ? 0.f : y1v[nf].y;
            s[nf][0] = (s[nf][0] + b00) * scale;
            s[nf][1] = (s[nf][1] + b01) * scale;
            s[nf][2] = (s[nf][2] + b10) * scale;
            s[nf][3] = (s[nf][3] + b11) * scale;
        }

        // ---- online softmax
        float m0 = -1e30f, m1 = -1e30f;
#pragma unroll
        for (int nf = 0; nf < 8; nf++) {
            m0 = fmaxf(m0, fmaxf(s[nf][0], s[nf][1]));
            m1 = fmaxf(m1, fmaxf(s[nf][2], s[nf][3]));
        }
        m0 = fmaxf(m0, __shfl_xor_sync(0xffffffffu, m0, 1));
        m0 = fmaxf(m0, __shfl_xor_sync(0xffffffffu, m0, 2));
        m1 = fmaxf(m1, __shfl_xor_sync(0xffffffffu, m1, 1));
        m1 = fmaxf(m1, __shfl_xor_sync(0xffffffffu, m1, 2));
        float mn0 = fmaxf(mr0, m0), mn1 = fmaxf(mr1, m1);
        float a0 = __expf(mr0 - mn0), a1 = __expf(mr1 - mn1);

        float l0 = 0.f, l1 = 0.f;
#pragma unroll
        for (int nf = 0; nf < 8; nf++) {
            float p0 = __expf(s[nf][0] - mn0);
            float p1 = __expf(s[nf][1] - mn0);
            float p2 = __expf(s[nf][2] - mn1);
            float p3 = __expf(s[nf][3] - mn1);
            l0 += p0 + p1; l1 += p2 + p3;
            int c = nf * 8 + 2 * tg;
            sP[r0 * 68 + c]           = f2tf(p0);
            sP[r0 * 68 + c + 1]       = f2tf(p1);
            sP[(r0 + 8) * 68 + c]     = f2tf(p2);
            sP[(r0 + 8) * 68 + c + 1] = f2tf(p3);
        }
        l0 += __shfl_xor_sync(0xffffffffu, l0, 1);
        l0 += __shfl_xor_sync(0xffffffffu, l0, 2);
        l1 += __shfl_xor_sync(0xffffffffu, l1, 1);
        l1 += __shfl_xor_sync(0xffffffffu, l1, 2);
        lr0 = lr0 * a0 + l0;
        lr1 = lr1 * a1 + l1;
        mr0 = mn0; mr1 = mn1;
#pragma unroll
        for (int nf = 0; nf < 8; nf++) {
            Oacc[nf][0] *= a0; Oacc[nf][1] *= a0;
            Oacc[nf][2] *= a1; Oacc[nf][3] *= a1;
        }
        __syncwarp();

        // ---- O += P @ V (raw bits)
#pragma unroll
        for (int kf = 0; kf < 8; kf++) {
            const int kk = kf * 8;
            unsigned pa[4];
            pa[0] = sP[r0 * 68 + kk + tg];
            pa[1] = sP[(r0 + 8) * 68 + kk + tg];
            pa[2] = sP[r0 * 68 + kk + tg + 4];
            pa[3] = sP[(r0 + 8) * 68 + kk + tg + 4];
#pragma unroll
            for (int nf = 0; nf < 8; nf++) {
                unsigned bb[2];
                bb[0] = __float_as_uint(Vs[(kk + tg) * 72 + nf * 8 + g]);
                bb[1] = __float_as_uint(Vs[(kk + tg + 4) * 72 + nf * 8 + g]);
                mma_tf32(Oacc[nf], pa, bb);
            }
        }
        __syncthreads();
    }

    float inv0 = 1.f / lr0, inv1 = 1.f / lr1;
#pragma unroll
    for (int nf = 0; nf < 8; nf++) {
        int col = n * 64 + nf * 8 + 2 * tg;
        *(float2*)(av + (size_t)(b * TTT + iR0) * DM + col) =
            make_float2(f2tf_f(Oacc[nf][0] * inv0), f2tf_f(Oacc[nf][1] * inv0));
        *(float2*)(av + (size_t)(b * TTT + iR1) * DM + col) =
            make_float2(f2tf_f(Oacc[nf][2] * inv1), f2tf_f(Oacc[nf][3] * inv1));
    }
}

// ---------------- residual add + LayerNorm over d=512 (rounded output) ----------------
__global__ void __launch_bounds__(128) add_ln(
    float* __restrict__ h, const float* __restrict__ a,
    const float* __restrict__ gs, const float* __restrict__ gb)
{
    const int row = blockIdx.x, tid = threadIdx.x;
    float* hp = h + (size_t)row * DM;
    const float* ap = a + (size_t)row * DM;
    float v[4];
    float s = 0.f;
#pragma unroll
    for (int j = 0; j < 4; j++) { int c = tid + j * 128; v[j] = hp[c] + ap[c]; s += v[j]; }

    __shared__ float red[8];
#pragma unroll
    for (int o = 16; o > 0; o >>= 1) s += __shfl_xor_sync(0xffffffffu, s, o);
    if ((tid & 31) == 0) red[tid >> 5] = s;
    __syncthreads();
    float mean = (red[0] + red[1] + red[2] + red[3]) * (1.f / 512.f);

    float var = 0.f;
#pragma unroll
    for (int j = 0; j < 4; j++) { float d = v[j] - mean; var += d * d; }
#pragma unroll
    for (int o = 16; o > 0; o >>= 1) var += __shfl_xor_sync(0xffffffffu, var, o);
    if ((tid & 31) == 0) red[4 + (tid >> 5)] = var;
    __syncthreads();
    var = (red[4] + red[5] + red[6] + red[7]) * (1.f / 512.f);
    float rs = rsqrtf(var + 1e-5f);
#pragma unroll
    for (int j = 0; j < 4; j++) {
        int c = tid + j * 128;
        hp[c] = f2tf_f((v[j] - mean) * rs * gs[c] + gb[c]);
    }
}

// ---------------- small helpers ----------------
__global__ void __launch_bounds__(256) pos_kernel(float* __restrict__ pos)
{
    int p = blockIdx.x;
    int f = threadIdx.x;
    float ps = (float)(TTT - 1 - p);
    float invf = 1.0f / powf(10000.0f, (float)(2 * f) / (float)DM);
    float ang = ps * invf;
    pos[(size_t)p * DM + f]       = f2tf_f(sinf(ang));
    pos[(size_t)p * DM + 256 + f] = f2tf_f(cosf(ang));
}

__global__ void transpose_x(const float* __restrict__ x, float* __restrict__ xT)
{
    __shared__ float tile[32][33];
    int b = blockIdx.z;
    int t0 = blockIdx.x * 32, c0 = blockIdx.y * 32;
    int tx = threadIdx.x, ty = threadIdx.y;
#pragma unroll
    for (int i = 0; i < 4; i++) {
        int c = c0 + ty + i * 8;
        tile[ty + i * 8][tx] = x[((size_t)b * CIN + c) * TTT + t0 + tx];
    }
    __syncthreads();
#pragma unroll
    for (int i = 0; i < 4; i++) {
        int t = t0 + ty + i * 8;
        xT[((size_t)b * TTT + t) * CIN + c0 + tx] = f2tf_f(tile[tx][ty + i * 8]);
    }
}

__global__ void transpose_cls(const float* __restrict__ tmp, float* __restrict__ outp)
{
    __shared__ float tile[32][33];
    int b = blockIdx.z;
    int t0 = blockIdx.x * 32, k0 = blockIdx.y * 32;
    int tx = threadIdx.x, ty = threadIdx.y;
#pragma unroll
    for (int i = 0; i < 4; i++) {
        int t = t0 + ty + i * 8;
        tile[ty + i * 8][tx] = tmp[((size_t)b * TTT + t) * NCLS + k0 + tx];
    }
    __syncthreads();
#pragma unroll
    for (int i = 0; i < 4; i++) {
        int k = k0 + ty + i * 8;
        outp[((size_t)b * NCLS + k) * TTT + t0 + tx] = tile[tx][ty + i * 8];
    }
}

// ---------------- host orchestration ----------------
extern "C" void kernel_launch(void* const* d_in, const int* in_sizes, int n_in,
                              void* d_out, int out_size)
{
    const float* x        = (const float*)d_in[0];
    const float* emb_w    = (const float*)d_in[1];
    const float* emb_b    = (const float*)d_in[2];
    const float* r_w_bias = (const float*)d_in[3];
    const float* r_r_bias = (const float*)d_in[4];
    const float* qkv_w    = (const float*)d_in[5];
    const float* qkv_b    = (const float*)d_in[6];
    const float* r_proj_w = (const float*)d_in[7];
    const float* o_w      = (const float*)d_in[8];
    const float* ln1_s    = (const float*)d_in[9];
    const float* ln1_b    = (const float*)d_in[10];
    const float* ff1_w    = (const float*)d_in[11];
    const float* ff1_b    = (const float*)d_in[12];
    const float* ff2_w    = (const float*)d_in[13];
    const float* ff2_b    = (const float*)d_in[14];
    const float* ln2_s    = (const float*)d_in[15];
    const float* ln2_b    = (const float*)d_in[16];
    const float* cls_w    = (const float*)d_in[17];
    const float* cls_b    = (const float*)d_in[18];
    float* outp = (float*)d_out;

    float *xT, *h, *tmp, *heads, *qw, *qr, *rk, *pos, *ff, *Bx, *av, *cls, *wb;
    cudaGetSymbolAddress((void**)&xT, g_xT);
    cudaGetSymbolAddress((void**)&h, g_h);
    cudaGetSymbolAddress((void**)&tmp, g_tmp);
    cudaGetSymbolAddress((void**)&heads, g_heads);
    cudaGetSymbolAddress((void**)&qw, g_qw);
    cudaGetSymbolAddress((void**)&qr, g_qr);
    cudaGetSymbolAddress((void**)&rk, g_rk);
    cudaGetSymbolAddress((void**)&pos, g_pos);
    cudaGetSymbolAddress((void**)&ff, g_ff);
    cudaGetSymbolAddress((void**)&Bx, g_Bx);
    cudaGetSymbolAddress((void**)&av, g_av);
    cudaGetSymbolAddress((void**)&cls, g_cls);
    cudaGetSymbolAddress((void**)&wb, g_wbuf);

    cudaFuncSetAttribute(gemm_tf32, cudaFuncAttributeMaxDynamicSharedMemorySize, GEMM_SMEM);
    cudaFuncSetAttribute(gemm_bd, cudaFuncAttributeMaxDynamicSharedMemorySize, GEMM_SMEM);
    cudaFuncSetAttribute(flash_attn, cudaFuncAttributeMaxDynamicSharedMemorySize, FA_SMEM);

    const float scale = 1.0f / 8.0f;

    // pre-round weights into tf32 scratch
    auto rc = [&](const float* src, float* dst, int n) {
        round_copy<<<(n / 4 + 255) / 256, 256>>>(src, dst, n);
    };
    rc(emb_w,    wb + W_EMB, DM * CIN);
    rc(qkv_w,    wb + W_QKV, NLAY * 3 * DM * DM);
    rc(r_proj_w, wb + W_RPJ, NLAY * DM * DM);
    rc(o_w,      wb + W_O,   NLAY * DM * DM);
    rc(ff1_w,    wb + W_FF1, NLAY * DI * DM);
    rc(ff2_w,    wb + W_FF2, NLAY * DM * DI);
    rc(cls_w,    wb + W_CLS, NCLS * DM);

    transpose_x<<<dim3(TTT / 32, CIN / 32, BB), dim3(32, 8)>>>(x, xT);
    pos_kernel<<<TTT, 256>>>(pos);

    // embed: h = xT @ emb_w^T + emb_b (store rounded)
    gemm_tf32<<<dim3(4, 32, 1), 256, GEMM_SMEM>>>(
        xT, CIN, 0, 0, wb + W_EMB, CIN, 0, 0, emb_b, h, DM, 0, 0, MR, DM, CIN, 0, 1,
        nullptr, nullptr, nullptr, nullptr);

    for (int l = 0; l < NLAY; l++) {
        const float* qkvW = wb + W_QKV + (size_t)l * 3 * DM * DM;
        const float* qkvB = qkv_b + (size_t)l * 3 * DM;
        const float* rW   = wb + W_RPJ + (size_t)l * DM * DM;
        const float* oW   = wb + W_O + (size_t)l * DM * DM;
        const float* f1W  = wb + W_FF1 + (size_t)l * DI * DM;
        const float* f1B  = ff1_b + (size_t)l * DI;
        const float* f2W  = wb + W_FF2 + (size_t)l * DM * DI;
        const float* f2B  = ff2_b + (size_t)l * DM;

        // heads = h @ qkv_w^T + b (rounded); fused qw/qr epilogue
        gemm_tf32<<<dim3(12, 32, 1), 256, GEMM_SMEM>>>(
            h, DM, 0, 0, qkvW, DM, 0, 0, qkvB, heads, 3 * DM, 0, 0, MR, 3 * DM, DM, 0, 1,
            r_w_bias, r_r_bias, qw, qr);

        // rk = pos @ r_proj_w^T (rounded)
        gemm_tf32<<<dim3(4, 16, 1), 256, GEMM_SMEM>>>(
            pos, DM, 0, 0, rW, DM, 0, 0, nullptr, rk, DM, 0, 0, TTT, DM, DM, 0, 1,
            nullptr, nullptr, nullptr, nullptr);

        // BDs[b,n] = rel_shift(qr @ rk_n^T)
        gemm_bd<<<dim3(16, 16, BB * NHD), 256, GEMM_SMEM>>>(
            qr, DM, (size_t)TTT * DM, 64,
            rk, DM, 64,
            Bx, (size_t)TTT * TTT);

        // fused: av = softmax((qw K^T + BDs) * scale) @ V
        flash_attn<<<dim3(TTT / 128, BB * NHD), 256, FA_SMEM>>>(qw, heads, Bx, av, scale);

        // attn_out = av @ o_w^T (tmp: only consumed by add_ln; rounding harmless)
        gemm_tf32<<<dim3(4, 32, 1), 256, GEMM_SMEM>>>(
            av, DM, 0, 0, oW, DM, 0, 0, nullptr, tmp, DM, 0, 0, MR, DM, DM, 0, 0,
            nullptr, nullptr, nullptr, nullptr);

        add_ln<<<MR, 128>>>(h, tmp, ln1_s + l * DM, ln1_b + l * DM);

        // ff = relu(h @ ff1_w^T + b) (rounded)
        gemm_tf32<<<dim3(16, 32, 1), 256, GEMM_SMEM>>>(
            h, DM, 0, 0, f1W, DM, 0, 0, f1B, ff, DI, 0, 0, MR, DI, DM, 1, 1,
            nullptr, nullptr, nullptr, nullptr);

        // tmp = ff @ ff2_w^T + b
        gemm_tf32<<<dim3(4, 32, 1), 256, GEMM_SMEM>>>(
            ff, DI, 0, 0, f2W, DI, 0, 0, f2B, tmp, DM, 0, 0, MR, DM, DI, 0, 0,
            nullptr, nullptr, nullptr, nullptr);

        add_ln<<<MR, 128>>>(h, tmp, ln2_s + l * DM, ln2_b + l * DM);
    }

    // cls = h @ cls_w^T + b (NOT rounded: final output path)
    gemm_tf32<<<dim3(1, 32, 1), 256, GEMM_SMEM>>>(
        h, DM, 0, 0, wb + W_CLS, DM, 0, 0, cls_b, cls, NCLS, 0, 0, MR, NCLS, DM, 0, 0,
        nullptr, nullptr, nullptr, nullptr);

    transpose_cls<<<dim3(TTT / 32, NCLS / 32, BB), dim3(32, 8)>>>(cls, outp);
}

// round 9
// speedup vs baseline: 1.1150x; 1.1150x over previous
#include <cuda_runtime.h>

// ---------------- problem constants ----------------
#define BB   2
#define TTT  2048
#define DM   512
#define NHD  8
#define DHD  64
#define NLAY 4
#define DI   2048
#define CIN  2048
#define NCLS 64
#define MR   (BB * TTT)   // 4096 token rows

// ---------------- scratch (device globals; no allocation allowed) ----------------
__device__ float g_xT[(size_t)BB * TTT * CIN];
__device__ float g_h[(size_t)MR * DM];
__device__ float g_tmp[(size_t)MR * DM];
__device__ float g_heads[(size_t)MR * 3 * DM];
__device__ float g_qw[(size_t)MR * DM];
__device__ float g_qr[(size_t)MR * DM];
__device__ float g_rk[(size_t)TTT * DM];
__device__ float g_pos[(size_t)TTT * DM];
__device__ float g_ff[(size_t)MR * DI];
__device__ float g_Bx[(size_t)BB * NHD * TTT * TTT];   // SHIFTED position scores (BDs layout)
__device__ float g_av[(size_t)MR * DM];
__device__ float g_cls[(size_t)MR * NCLS];
// pre-rounded (tf32) weights: emb | qkv | rproj | o | ff1 | ff2 | cls
#define W_EMB  0
#define W_QKV  (W_EMB + DM * CIN)
#define W_RPJ  (W_QKV + NLAY * 3 * DM * DM)
#define W_O    (W_RPJ + NLAY * DM * DM)
#define W_FF1  (W_O + NLAY * DM * DM)
#define W_FF2  (W_FF1 + NLAY * DI * DM)
#define W_CLS  (W_FF2 + NLAY * DM * DI)
#define W_END  (W_CLS + NCLS * DM)
__device__ float g_wbuf[(size_t)W_END];

// ---------------- tf32 / cp.async helpers ----------------
__device__ __forceinline__ unsigned f2tf(float x) {
    unsigned u;
    asm("cvt.rna.tf32.f32 %0, %1;" : "=r"(u) : "f"(x));
    return u;
}
__device__ __forceinline__ float f2tf_f(float x) { return __uint_as_float(f2tf(x)); }

__device__ __forceinline__ void mma_tf32(float* c, const unsigned* a, const unsigned* b) {
    asm volatile(
        "mma.sync.aligned.m16n8k8.row.col.f32.tf32.tf32.f32 "
        "{%0,%1,%2,%3}, {%4,%5,%6,%7}, {%8,%9}, {%0,%1,%2,%3};"
        : "+f"(c[0]), "+f"(c[1]), "+f"(c[2]), "+f"(c[3])
        : "r"(a[0]), "r"(a[1]), "r"(a[2]), "r"(a[3]), "r"(b[0]), "r"(b[1]));
}

__device__ __forceinline__ void cp16(void* dst, const void* src, int srcbytes) {
    unsigned u = (unsigned)__cvta_generic_to_shared(dst);
    asm volatile("cp.async.cg.shared.global [%0], [%1], 16, %2;"
                 :: "r"(u), "l"(src), "r"(srcbytes));
}
__device__ __forceinline__ void cp_commit() {
    asm volatile("cp.async.commit_group;");
}

// ---------------- pre-round weights to tf32 (bitwise in fp32 container) ----------------
__global__ void __launch_bounds__(256) round_copy(const float* __restrict__ src,
                                                 float* __restrict__ dst, int n)
{
    int i = (blockIdx.x * 256 + threadIdx.x) * 4;
    if (i < n) {
        float4 v = *(const float4*)(src + i);
        v.x = f2tf_f(v.x); v.y = f2tf_f(v.y); v.z = f2tf_f(v.z); v.w = f2tf_f(v.w);
        *(float4*)(dst + i) = v;
    }
}

// ---------------- TF32 tensor-core GEMM, 2-stage cp.async ----------------
// stride 40 -> conflict-free LDS.64 paired-k fragment loads.
// CVTA=1: A fragments converted (A in fp32); CVTA=0: A pre-rounded (raw bits).
// B always pre-rounded (raw bits).
#define GSM_STAGE (128 * 40)
#define GEMM_SMEM (4 * GSM_STAGE * 4)   // 81920 B

template<int CVTA>
__global__ void __launch_bounds__(256, 2) gemm_tf32(
    const float* __restrict__ A, int lda, size_t sAb, size_t sAn,
    const float* __restrict__ B, int ldb, size_t sBb, size_t sBn,
    const float* __restrict__ bias,
    float* __restrict__ C, int ldc, size_t sCb, size_t sCn,
    int M, int N, int K, int relu, int roundC,
    const float* __restrict__ rwb, const float* __restrict__ rrb,
    float* __restrict__ qwO, float* __restrict__ qrO)
{
    const int z = blockIdx.z, zb = z >> 3, zn = z & 7;
    A += (size_t)zb * sAb + (size_t)zn * sAn;
    B += (size_t)zb * sBb + (size_t)zn * sBn;
    C += (size_t)zb * sCb + (size_t)zn * sCn;

    extern __shared__ float gsm[];
    float* AsBase = gsm;
    float* BsBase = gsm + 2 * GSM_STAGE;

    const int tid = threadIdx.x;
    const int warp = tid >> 5, lane = tid & 31;
    const int wm = warp >> 2, wn = warp & 3;
    const int g = lane >> 2, tg = lane & 3;
    const int m0 = blockIdx.y * 128, n0 = blockIdx.x * 128;

    float acc[4][4][4];
#pragma unroll
    for (int mt = 0; mt < 4; mt++)
#pragma unroll
        for (int nt = 0; nt < 4; nt++)
#pragma unroll
            for (int i = 0; i < 4; i++) acc[mt][nt][i] = 0.f;

    const int KT = K >> 5;

    auto load_stage = [&](int st, int k0) {
#pragma unroll
        for (int i = 0; i < 4; i++) {
            int idx = tid + i * 256;
            int row = idx >> 3;
            int kq = (idx & 7) * 4;
            cp16(&AsBase[st * GSM_STAGE + row * 40 + kq],
                 A + (size_t)(m0 + row) * lda + k0 + kq, 16);
        }
#pragma unroll
        for (int i = 0; i < 4; i++) {
            int idx = tid + i * 256;
            int row = idx >> 3;
            int kq = (idx & 7) * 4;
            int ok = (n0 + row) < N;
            cp16(&BsBase[st * GSM_STAGE + row * 40 + kq],
                 B + (size_t)(ok ? (n0 + row) : 0) * ldb + k0 + kq, ok ? 16 : 0);
        }
        cp_commit();
    };

    load_stage(0, 0);

    for (int kt = 0; kt < KT; kt++) {
        const int st = kt & 1;
        if (kt + 1 < KT) {
            load_stage(st ^ 1, (kt + 1) * 32);
            asm volatile("cp.async.wait_group 1;");
        } else {
            asm volatile("cp.async.wait_group 0;");
        }
        __syncthreads();

        const float* Asl = AsBase + st * GSM_STAGE;
        const float* Bsl = BsBase + st * GSM_STAGE;

#pragma unroll
        for (int ks = 0; ks < 4; ks++) {
            const int kk = ks * 8 + 2 * tg;   // paired-k permutation {tg,tg+4}->{2tg,2tg+1}
            unsigned a[4][4], bb[4][2];
#pragma unroll
            for (int mt = 0; mt < 4; mt++) {
                int r = wm * 64 + mt * 16;
                float2 p0 = *(const float2*)(Asl + (r + g) * 40 + kk);
                float2 p1 = *(const float2*)(Asl + (r + g + 8) * 40 + kk);
                if (CVTA) {
                    a[mt][0] = f2tf(p0.x); a[mt][2] = f2tf(p0.y);
                    a[mt][1] = f2tf(p1.x); a[mt][3] = f2tf(p1.y);
                } else {
                    a[mt][0] = __float_as_uint(p0.x); a[mt][2] = __float_as_uint(p0.y);
                    a[mt][1] = __float_as_uint(p1.x); a[mt][3] = __float_as_uint(p1.y);
                }
            }
#pragma unroll
            for (int nt = 0; nt < 4; nt++) {
                int c = wn * 32 + nt * 8;
                float2 pb = *(const float2*)(Bsl + (c + g) * 40 + kk);
                bb[nt][0] = __float_as_uint(pb.x);
                bb[nt][1] = __float_as_uint(pb.y);
            }
#pragma unroll
            for (int mt = 0; mt < 4; mt++)
#pragma unroll
                for (int nt = 0; nt < 4; nt++)
                    mma_tf32(acc[mt][nt], a[mt], bb[nt]);
        }
        __syncthreads();
    }

#pragma unroll
    for (int mt = 0; mt < 4; mt++) {
        int r0 = m0 + wm * 64 + mt * 16 + g;
#pragma unroll
        for (int nt = 0; nt < 4; nt++) {
            int c0 = n0 + wn * 32 + nt * 8 + tg * 2;
            if (c0 < N) {
                float b0v = bias ? bias[c0] : 0.f;
                float b1v = bias ? bias[c0 + 1] : 0.f;
                float v0 = acc[mt][nt][0] + b0v;
                float v1 = acc[mt][nt][1] + b1v;
                float v2 = acc[mt][nt][2] + b0v;
                float v3 = acc[mt][nt][3] + b1v;
                if (relu) {
                    v0 = fmaxf(v0, 0.f); v1 = fmaxf(v1, 0.f);
                    v2 = fmaxf(v2, 0.f); v3 = fmaxf(v3, 0.f);
                }
                float s0 = v0, s1 = v1, s2 = v2, s3 = v3;
                if (roundC) {
                    s0 = f2tf_f(v0); s1 = f2tf_f(v1); s2 = f2tf_f(v2); s3 = f2tf_f(v3);
                }
                *(float2*)(C + (size_t)r0 * ldc + c0) = make_float2(s0, s1);
                *(float2*)(C + (size_t)(r0 + 8) * ldc + c0) = make_float2(s2, s3);
                if (qwO && c0 < DM) {
                    float w0 = rwb[c0], w1 = rwb[c0 + 1];
                    float r0b = rrb[c0], r1b = rrb[c0 + 1];
                    *(float2*)(qwO + (size_t)r0 * DM + c0) =
                        make_float2(f2tf_f(v0 + w0), f2tf_f(v1 + w1));
                    *(float2*)(qwO + (size_t)(r0 + 8) * DM + c0) =
                        make_float2(f2tf_f(v2 + w0), f2tf_f(v3 + w1));
                    *(float2*)(qrO + (size_t)r0 * DM + c0) =
                        make_float2(f2tf_f(v0 + r0b), f2tf_f(v1 + r1b));
                    *(float2*)(qrO + (size_t)(r0 + 8) * DM + c0) =
                        make_float2(f2tf_f(v2 + r0b), f2tf_f(v3 + r1b));
                }
            }
        }
    }
}

// ---------------- BD GEMM with shifted-scatter epilogue ----------------
__device__ __forceinline__ void bd_store(float* __restrict__ BDs, int i, int c, float v) {
    int thr = TTT - 1 - i;
    if (c >= thr)      BDs[(size_t)i * TTT + (c - thr)] = v;
    else if (i > 0)    BDs[(size_t)(i - 1) * TTT + (c + i + 1)] = v;
}

__global__ void __launch_bounds__(256, 2) gemm_bd(
    const float* __restrict__ A, int lda, size_t sAb, size_t sAn,   // qr (tf32-rounded)
    const float* __restrict__ B, int ldb, size_t sBn,               // rk (tf32-rounded)
    float* __restrict__ C, size_t sCbn)                             // BDs (fp32)
{
    const int z = blockIdx.z, zb = z >> 3, zn = z & 7;
    A += (size_t)zb * sAb + (size_t)zn * sAn;
    B += (size_t)zn * sBn;
    C += (size_t)z * sCbn;

    extern __shared__ float gsm[];
    float* AsBase = gsm;
    float* BsBase = gsm + 2 * GSM_STAGE;

    const int tid = threadIdx.x;
    const int warp = tid >> 5, lane = tid & 31;
    const int wm = warp >> 2, wn = warp & 3;
    const int g = lane >> 2, tg = lane & 3;
    const int m0 = blockIdx.y * 128, n0 = blockIdx.x * 128;

    float acc[4][4][4];
#pragma unroll
    for (int mt = 0; mt < 4; mt++)
#pragma unroll
        for (int nt = 0; nt < 4; nt++)
#pragma unroll
            for (int i = 0; i < 4; i++) acc[mt][nt][i] = 0.f;

    auto load_stage = [&](int st, int k0) {
#pragma unroll
        for (int i = 0; i < 4; i++) {
            int idx = tid + i * 256;
            int row = idx >> 3;
            int kq = (idx & 7) * 4;
            cp16(&AsBase[st * GSM_STAGE + row * 40 + kq],
                 A + (size_t)(m0 + row) * lda + k0 + kq, 16);
        }
#pragma unroll
        for (int i = 0; i < 4; i++) {
            int idx = tid + i * 256;
            int row = idx >> 3;
            int kq = (idx & 7) * 4;
            cp16(&BsBase[st * GSM_STAGE + row * 40 + kq],
                 B + (size_t)(n0 + row) * ldb + k0 + kq, 16);
        }
        cp_commit();
    };

    load_stage(0, 0);

#pragma unroll
    for (int kt = 0; kt < 2; kt++) {
        const int st = kt & 1;
        if (kt == 0) {
            load_stage(1, 32);
            asm volatile("cp.async.wait_group 1;");
        } else {
            asm volatile("cp.async.wait_group 0;");
        }
        __syncthreads();

        const float* Asl = AsBase + st * GSM_STAGE;
        const float* Bsl = BsBase + st * GSM_STAGE;

#pragma unroll
        for (int ks = 0; ks < 4; ks++) {
            const int kk = ks * 8 + 2 * tg;
            unsigned a[4][4], bb[4][2];
#pragma unroll
            for (int mt = 0; mt < 4; mt++) {
                int r = wm * 64 + mt * 16;
                float2 p0 = *(const float2*)(Asl + (r + g) * 40 + kk);
                float2 p1 = *(const float2*)(Asl + (r + g + 8) * 40 + kk);
                a[mt][0] = __float_as_uint(p0.x);
                a[mt][2] = __float_as_uint(p0.y);
                a[mt][1] = __float_as_uint(p1.x);
                a[mt][3] = __float_as_uint(p1.y);
            }
#pragma unroll
            for (int nt = 0; nt < 4; nt++) {
                int c = wn * 32 + nt * 8;
                float2 pb = *(const float2*)(Bsl + (c + g) * 40 + kk);
                bb[nt][0] = __float_as_uint(pb.x);
                bb[nt][1] = __float_as_uint(pb.y);
            }
#pragma unroll
            for (int mt = 0; mt < 4; mt++)
#pragma unroll
                for (int nt = 0; nt < 4; nt++)
                    mma_tf32(acc[mt][nt], a[mt], bb[nt]);
        }
        __syncthreads();
    }

#pragma unroll
    for (int mt = 0; mt < 4; mt++) {
        int i0r = m0 + wm * 64 + mt * 16 + g;
        int i1r = i0r + 8;
#pragma unroll
        for (int nt = 0; nt < 4; nt++) {
            int c0 = n0 + wn * 32 + nt * 8 + tg * 2;
            bd_store(C, i0r, c0,     acc[mt][nt][0]);
            bd_store(C, i0r, c0 + 1, acc[mt][nt][1]);
            bd_store(C, i1r, c0,     acc[mt][nt][2]);
            bd_store(C, i1r, c0 + 1, acc[mt][nt][3]);
        }
    }
}

// ---------------- fused flash attention (all MMA inputs pre-rounded) ----------------
#define SP_ELEMS (128 * 68)
#define SK_ELEMS (64 * 68)
#define SV_ELEMS (64 * 72)
#define FA_SMEM ((SP_ELEMS + 2 * SK_ELEMS + 2 * SV_ELEMS) * 4)

__global__ void __launch_bounds__(256, 1) flash_attn(
    const float* __restrict__ qw,     // [MR][512] tf32-rounded
    const float* __restrict__ heads,  // [MR][1536] tf32-rounded; K at +512, V at +1024
    const float* __restrict__ BDs,    // [16][T][T] pre-shifted fp32
    float* __restrict__ av,           // [MR][512]
    float scale)
{
    extern __shared__ unsigned smem_u[];
    unsigned* sP = smem_u;                                   // [128][68]
    float* sK = (float*)(smem_u + SP_ELEMS);                 // [2][64][68]
    float* sV = (float*)(smem_u + SP_ELEMS) + 2 * SK_ELEMS;  // [2][64][72]

    const int tid = threadIdx.x;
    const int w = tid >> 5, lane = tid & 31;
    const int g = lane >> 2, tg = lane & 3;
    const int i0 = blockIdx.x * 128;
    const int bn = blockIdx.y;
    const int b = bn >> 3, n = bn & 7;

    const float* Qb = qw + ((size_t)b * TTT) * DM + n * 64;
    const float* Kb = heads + DM + ((size_t)b * TTT) * (3 * DM) + n * 64;
    const float* Vb = heads + 2 * DM + ((size_t)b * TTT) * (3 * DM) + n * 64;
    const float* Bb = BDs + (size_t)bn * TTT * TTT;

    auto kv_load = [&](int st, int j0) {
#pragma unroll
        for (int it = 0; it < 4; it++) {
            int idx = tid + it * 256;
            int row = idx >> 4, c4 = (idx & 15) * 4;
            cp16(&sK[st * SK_ELEMS + row * 68 + c4],
                 Kb + (size_t)(j0 + row) * (3 * DM) + c4, 16);
        }
#pragma unroll
        for (int it = 0; it < 4; it++) {
            int idx = tid + it * 256;
            int row = idx >> 4, c4 = (idx & 15) * 4;
            cp16(&sV[st * SV_ELEMS + row * 72 + c4],
                 Vb + (size_t)(j0 + row) * (3 * DM) + c4, 16);
        }
        cp_commit();
    };

    kv_load(0, 0);

#pragma unroll
    for (int it = 0; it < 8; it++) {
        int idx = tid + it * 256;
        int row = idx >> 4, c4 = (idx & 15) * 4;
        float4 v = *(const float4*)(Qb + (size_t)(i0 + row) * DM + c4);
        sP[row * 68 + c4 + 0] = __float_as_uint(v.x);
        sP[row * 68 + c4 + 1] = __float_as_uint(v.y);
        sP[row * 68 + c4 + 2] = __float_as_uint(v.z);
        sP[row * 68 + c4 + 3] = __float_as_uint(v.w);
    }
    __syncthreads();

    const int r0 = 16 * w + g;
    const int iR0 = i0 + r0, iR1 = iR0 + 8;
    const float* BDr0 = Bb + (size_t)iR0 * TTT;
    const float* BDr1 = Bb + (size_t)iR1 * TTT;

    unsigned qa[8][4];
#pragma unroll
    for (int kf = 0; kf < 8; kf++) {
        qa[kf][0] = sP[r0 * 68 + kf * 8 + tg];
        qa[kf][1] = sP[(r0 + 8) * 68 + kf * 8 + tg];
        qa[kf][2] = sP[r0 * 68 + kf * 8 + tg + 4];
        qa[kf][3] = sP[(r0 + 8) * 68 + kf * 8 + tg + 4];
    }

    float Oacc[8][4];
#pragma unroll
    for (int nf = 0; nf < 8; nf++)
#pragma unroll
        for (int i = 0; i < 4; i++) Oacc[nf][i] = 0.f;
    float mr0 = -1e30f, mr1 = -1e30f, lr0 = 0.f, lr1 = 0.f;

    for (int jt = 0; jt < TTT / 64; jt++) {
        const int st = jt & 1;
        const int j0 = jt * 64;
        if (jt + 1 < TTT / 64) {
            kv_load(st ^ 1, (jt + 1) * 64);
            asm volatile("cp.async.wait_group 1;");
        } else {
            asm volatile("cp.async.wait_group 0;");
        }
        __syncthreads();

        const float* Ks = sK + st * SK_ELEMS;
        const float* Vs = sV + st * SV_ELEMS;

        float2 y0v[8], y1v[8];
#pragma unroll
        for (int nf = 0; nf < 8; nf++) {
            int j = j0 + nf * 8 + 2 * tg;
            y0v[nf] = *(const float2*)(BDr0 + j);
            y1v[nf] = *(const float2*)(BDr1 + j);
        }

        // ---- S = Q @ K^T (raw bits)
        float s[8][4];
#pragma unroll
        for (int nf = 0; nf < 8; nf++)
#pragma unroll
            for (int i = 0; i < 4; i++) s[nf][i] = 0.f;
#pragma unroll
        for (int kf = 0; kf < 8; kf++) {
            const int kk = kf * 8;
#pragma unroll
            for (int nf = 0; nf < 8; nf++) {
                unsigned bb[2];
                bb[0] = __float_as_uint(Ks[(nf * 8 + g) * 68 + kk + tg]);
                bb[1] = __float_as_uint(Ks[(nf * 8 + g) * 68 + kk + tg + 4]);
                mma_tf32(s[nf], qa[kf], bb);
            }
        }

#pragma unroll
        for (int nf = 0; nf < 8; nf++) {
            int j = j0 + nf * 8 + 2 * tg;
            float b00 = (j     == iR0 + 1) ? 0.f : y0v[nf].x;
            float b01 = (j + 1 == iR0 + 1) ? 0.f : y0v[nf].y;
            float b10 = (j     == iR1 + 1) ? 0.f : y1v[nf].x;
            float b11 = (j + 1 == iR1 + 1) ? 0.f : y1v[nf].y;
            s[nf][0] = (s[nf][0] + b00) * scale;
            s[nf][1] = (s[nf][1] + b01) * scale;
            s[nf][2] = (s[nf][2] + b10) * scale;
            s[nf][3] = (s[nf][3] + b11) * scale;
        }

        // ---- online softmax
        float m0 = -1e30f, m1 = -1e30f;
#pragma unroll
        for (int nf = 0; nf < 8; nf++) {
            m0 = fmaxf(m0, fmaxf(s[nf][0], s[nf][1]));
            m1 = fmaxf(m1, fmaxf(s[nf][2], s[nf][3]));
        }
        m0 = fmaxf(m0, __shfl_xor_sync(0xffffffffu, m0, 1));
        m0 = fmaxf(m0, __shfl_xor_sync(0xffffffffu, m0, 2));
        m1 = fmaxf(m1, __shfl_xor_sync(0xffffffffu, m1, 1));
        m1 = fmaxf(m1, __shfl_xor_sync(0xffffffffu, m1, 2));
        float mn0 = fmaxf(mr0, m0), mn1 = fmaxf(mr1, m1);
        float a0 = __expf(mr0 - mn0), a1 = __expf(mr1 - mn1);

        float l0 = 0.f, l1 = 0.f;
#pragma unroll
        for (int nf = 0; nf < 8; nf++) {
            float p0 = __expf(s[nf][0] - mn0);
            float p1 = __expf(s[nf][1] - mn0);
            float p2 = __expf(s[nf][2] - mn1);
            float p3 = __expf(s[nf][3] - mn1);
            l0 += p0 + p1; l1 += p2 + p3;
            int c = nf * 8 + 2 * tg;
            sP[r0 * 68 + c]           = f2tf(p0);
            sP[r0 * 68 + c + 1]       = f2tf(p1);
            sP[(r0 + 8) * 68 + c]     = f2tf(p2);
            sP[(r0 + 8) * 68 + c + 1] = f2tf(p3);
        }
        l0 += __shfl_xor_sync(0xffffffffu, l0, 1);
        l0 += __shfl_xor_sync(0xffffffffu, l0, 2);
        l1 += __shfl_xor_sync(0xffffffffu, l1, 1);
        l1 += __shfl_xor_sync(0xffffffffu, l1, 2);
        lr0 = lr0 * a0 + l0;
        lr1 = lr1 * a1 + l1;
        mr0 = mn0; mr1 = mn1;
#pragma unroll
        for (int nf = 0; nf < 8; nf++) {
            Oacc[nf][0] *= a0; Oacc[nf][1] *= a0;
            Oacc[nf][2] *= a1; Oacc[nf][3] *= a1;
        }
        __syncwarp();

        // ---- O += P @ V (raw bits)
#pragma unroll
        for (int kf = 0; kf < 8; kf++) {
            const int kk = kf * 8;
            unsigned pa[4];
            pa[0] = sP[r0 * 68 + kk + tg];
            pa[1] = sP[(r0 + 8) * 68 + kk + tg];
            pa[2] = sP[r0 * 68 + kk + tg + 4];
            pa[3] = sP[(r0 + 8) * 68 + kk + tg + 4];
#pragma unroll
            for (int nf = 0; nf < 8; nf++) {
                unsigned bb[2];
                bb[0] = __float_as_uint(Vs[(kk + tg) * 72 + nf * 8 + g]);
                bb[1] = __float_as_uint(Vs[(kk + tg + 4) * 72 + nf * 8 + g]);
                mma_tf32(Oacc[nf], pa, bb);
            }
        }
        __syncthreads();
    }

    float inv0 = 1.f / lr0, inv1 = 1.f / lr1;
#pragma unroll
    for (int nf = 0; nf < 8; nf++) {
        int col = n * 64 + nf * 8 + 2 * tg;
        *(float2*)(av + (size_t)(b * TTT + iR0) * DM + col) =
            make_float2(f2tf_f(Oacc[nf][0] * inv0), f2tf_f(Oacc[nf][1] * inv0));
        *(float2*)(av + (size_t)(b * TTT + iR1) * DM + col) =
            make_float2(f2tf_f(Oacc[nf][2] * inv1), f2tf_f(Oacc[nf][3] * inv1));
    }
}

// ---------------- residual add + LayerNorm over d=512 (fp32 residual stream) ----------------
__global__ void __launch_bounds__(128) add_ln(
    float* __restrict__ h, const float* __restrict__ a,
    const float* __restrict__ gs, const float* __restrict__ gb)
{
    const int row = blockIdx.x, tid = threadIdx.x;
    float* hp = h + (size_t)row * DM;
    const float* ap = a + (size_t)row * DM;
    float v[4];
    float s = 0.f;
#pragma unroll
    for (int j = 0; j < 4; j++) { int c = tid + j * 128; v[j] = hp[c] + ap[c]; s += v[j]; }

    __shared__ float red[8];
#pragma unroll
    for (int o = 16; o > 0; o >>= 1) s += __shfl_xor_sync(0xffffffffu, s, o);
    if ((tid & 31) == 0) red[tid >> 5] = s;
    __syncthreads();
    float mean = (red[0] + red[1] + red[2] + red[3]) * (1.f / 512.f);

    float var = 0.f;
#pragma unroll
    for (int j = 0; j < 4; j++) { float d = v[j] - mean; var += d * d; }
#pragma unroll
    for (int o = 16; o > 0; o >>= 1) var += __shfl_xor_sync(0xffffffffu, var, o);
    if ((tid & 31) == 0) red[4 + (tid >> 5)] = var;
    __syncthreads();
    var = (red[4] + red[5] + red[6] + red[7]) * (1.f / 512.f);
    float rs = rsqrtf(var + 1e-5f);
#pragma unroll
    for (int j = 0; j < 4; j++) {
        int c = tid + j * 128;
        hp[c] = (v[j] - mean) * rs * gs[c] + gb[c];
    }
}

// ---------------- small helpers ----------------
__global__ void __launch_bounds__(256) pos_kernel(float* __restrict__ pos)
{
    int p = blockIdx.x;
    int f = threadIdx.x;
    float ps = (float)(TTT - 1 - p);
    float invf = 1.0f / powf(10000.0f, (float)(2 * f) / (float)DM);
    float ang = ps * invf;
    pos[(size_t)p * DM + f]       = f2tf_f(sinf(ang));
    pos[(size_t)p * DM + 256 + f] = f2tf_f(cosf(ang));
}

__global__ void transpose_x(const float* __restrict__ x, float* __restrict__ xT)
{
    __shared__ float tile[32][33];
    int b = blockIdx.z;
    int t0 = blockIdx.x * 32, c0 = blockIdx.y * 32;
    int tx = threadIdx.x, ty = threadIdx.y;
#pragma unroll
    for (int i = 0; i < 4; i++) {
        int c = c0 + ty + i * 8;
        tile[ty + i * 8][tx] = x[((size_t)b * CIN + c) * TTT + t0 + tx];
    }
    __syncthreads();
#pragma unroll
    for (int i = 0; i < 4; i++) {
        int t = t0 + ty + i * 8;
        xT[((size_t)b * TTT + t) * CIN + c0 + tx] = f2tf_f(tile[tx][ty + i * 8]);
    }
}

__global__ void transpose_cls(const float* __restrict__ tmp, float* __restrict__ outp)
{
    __shared__ float tile[32][33];
    int b = blockIdx.z;
    int t0 = blockIdx.x * 32, k0 = blockIdx.y * 32;
    int tx = threadIdx.x, ty = threadIdx.y;
#pragma unroll
    for (int i = 0; i < 4; i++) {
        int t = t0 + ty + i * 8;
        tile[ty + i * 8][tx] = tmp[((size_t)b * TTT + t) * NCLS + k0 + tx];
    }
    __syncthreads();
#pragma unroll
    for (int i = 0; i < 4; i++) {
        int k = k0 + ty + i * 8;
        outp[((size_t)b * NCLS + k) * TTT + t0 + tx] = tile[tx][ty + i * 8];
    }
}

// ---------------- host orchestration ----------------
extern "C" void kernel_launch(void* const* d_in, const int* in_sizes, int n_in,
                              void* d_out, int out_size)
{
    const float* x        = (const float*)d_in[0];
    const float* emb_w    = (const float*)d_in[1];
    const float* emb_b    = (const float*)d_in[2];
    const float* r_w_bias = (const float*)d_in[3];
    const float* r_r_bias = (const float*)d_in[4];
    const float* qkv_w    = (const float*)d_in[5];
    const float* qkv_b    = (const float*)d_in[6];
    const float* r_proj_w = (const float*)d_in[7];
    const float* o_w      = (const float*)d_in[8];
    const float* ln1_s    = (const float*)d_in[9];
    const float* ln1_b    = (const float*)d_in[10];
    const float* ff1_w    = (const float*)d_in[11];
    const float* ff1_b    = (const float*)d_in[12];
    const float* ff2_w    = (const float*)d_in[13];
    const float* ff2_b    = (const float*)d_in[14];
    const float* ln2_s    = (const float*)d_in[15];
    const float* ln2_b    = (const float*)d_in[16];
    const float* cls_w    = (const float*)d_in[17];
    const float* cls_b    = (const float*)d_in[18];
    float* outp = (float*)d_out;

    float *xT, *h, *tmp, *heads, *qw, *qr, *rk, *pos, *ff, *Bx, *av, *cls, *wb;
    cudaGetSymbolAddress((void**)&xT, g_xT);
    cudaGetSymbolAddress((void**)&h, g_h);
    cudaGetSymbolAddress((void**)&tmp, g_tmp);
    cudaGetSymbolAddress((void**)&heads, g_heads);
    cudaGetSymbolAddress((void**)&qw, g_qw);
    cudaGetSymbolAddress((void**)&qr, g_qr);
    cudaGetSymbolAddress((void**)&rk, g_rk);
    cudaGetSymbolAddress((void**)&pos, g_pos);
    cudaGetSymbolAddress((void**)&ff, g_ff);
    cudaGetSymbolAddress((void**)&Bx, g_Bx);
    cudaGetSymbolAddress((void**)&av, g_av);
    cudaGetSymbolAddress((void**)&cls, g_cls);
    cudaGetSymbolAddress((void**)&wb, g_wbuf);

    cudaFuncSetAttribute(gemm_tf32<0>, cudaFuncAttributeMaxDynamicSharedMemorySize, GEMM_SMEM);
    cudaFuncSetAttribute(gemm_tf32<1>, cudaFuncAttributeMaxDynamicSharedMemorySize, GEMM_SMEM);
    cudaFuncSetAttribute(gemm_bd, cudaFuncAttributeMaxDynamicSharedMemorySize, GEMM_SMEM);
    cudaFuncSetAttribute(flash_attn, cudaFuncAttributeMaxDynamicSharedMemorySize, FA_SMEM);

    const float scale = 1.0f / 8.0f;

    // pre-round weights into tf32 scratch
    auto rc = [&](const float* src, float* dst, int n) {
        round_copy<<<(n / 4 + 255) / 256, 256>>>(src, dst, n);
    };
    rc(emb_w,    wb + W_EMB, DM * CIN);
    rc(qkv_w,    wb + W_QKV, NLAY * 3 * DM * DM);
    rc(r_proj_w, wb + W_RPJ, NLAY * DM * DM);
    rc(o_w,      wb + W_O,   NLAY * DM * DM);
    rc(ff1_w,    wb + W_FF1, NLAY * DI * DM);
    rc(ff2_w,    wb + W_FF2, NLAY * DM * DI);
    rc(cls_w,    wb + W_CLS, NCLS * DM);

    transpose_x<<<dim3(TTT / 32, CIN / 32, BB), dim3(32, 8)>>>(x, xT);
    pos_kernel<<<TTT, 256>>>(pos);

    // embed: h = xT(rounded) @ emb_w^T + emb_b ; h stays fp32
    gemm_tf32<0><<<dim3(4, 32, 1), 256, GEMM_SMEM>>>(
        xT, CIN, 0, 0, wb + W_EMB, CIN, 0, 0, emb_b, h, DM, 0, 0, MR, DM, CIN, 0, 0,
        nullptr, nullptr, nullptr, nullptr);

    for (int l = 0; l < NLAY; l++) {
        const float* qkvW = wb + W_QKV + (size_t)l * 3 * DM * DM;
        const float* qkvB = qkv_b + (size_t)l * 3 * DM;
        const float* rW   = wb + W_RPJ + (size_t)l * DM * DM;
        const float* oW   = wb + W_O + (size_t)l * DM * DM;
        const float* f1W  = wb + W_FF1 + (size_t)l * DI * DM;
        const float* f1B  = ff1_b + (size_t)l * DI;
        const float* f2W  = wb + W_FF2 + (size_t)l * DM * DI;
        const float* f2B  = ff2_b + (size_t)l * DM;

        // heads = h @ qkv_w^T + b (A converted; heads rounded = MMA-only); qw/qr epilogue
        gemm_tf32<1><<<dim3(12, 32, 1), 256, GEMM_SMEM>>>(
            h, DM, 0, 0, qkvW, DM, 0, 0, qkvB, heads, 3 * DM, 0, 0, MR, 3 * DM, DM, 0, 1,
            r_w_bias, r_r_bias, qw, qr);

        // rk = pos(rounded) @ r_proj_w^T (rk rounded = MMA-only)
        gemm_tf32<0><<<dim3(4, 16, 1), 256, GEMM_SMEM>>>(
            pos, DM, 0, 0, rW, DM, 0, 0, nullptr, rk, DM, 0, 0, TTT, DM, DM, 0, 1,
            nullptr, nullptr, nullptr, nullptr);

        // BDs[b,n] = rel_shift(qr @ rk_n^T)
        gemm_bd<<<dim3(16, 16, BB * NHD), 256, GEMM_SMEM>>>(
            qr, DM, (size_t)TTT * DM, 64,
            rk, DM, 64,
            Bx, (size_t)TTT * TTT);

        // fused: av = softmax((qw K^T + BDs) * scale) @ V
        flash_attn<<<dim3(TTT / 128, BB * NHD), 256, FA_SMEM>>>(qw, heads, Bx, av, scale);

        // attn_out = av(rounded) @ o_w^T ; tmp fp32 (residual input)
        gemm_tf32<0><<<dim3(4, 32, 1), 256, GEMM_SMEM>>>(
            av, DM, 0, 0, oW, DM, 0, 0, nullptr, tmp, DM, 0, 0, MR, DM, DM, 0, 0,
            nullptr, nullptr, nullptr, nullptr);

        add_ln<<<MR, 128>>>(h, tmp, ln1_s + l * DM, ln1_b + l * DM);

        // ff = relu(h @ ff1_w^T + b) (A converted; ff rounded = MMA-only)
        gemm_tf32<1><<<dim3(16, 32, 1), 256, GEMM_SMEM>>>(
            h, DM, 0, 0, f1W, DM, 0, 0, f1B, ff, DI, 0, 0, MR, DI, DM, 1, 1,
            nullptr, nullptr, nullptr, nullptr);

        // tmp = ff(rounded) @ ff2_w^T + b ; tmp fp32
        gemm_tf32<0><<<dim3(4, 32, 1), 256, GEMM_SMEM>>>(
            ff, DI, 0, 0, f2W, DI, 0, 0, f2B, tmp, DM, 0, 0, MR, DM, DI, 0, 0,
            nullptr, nullptr, nullptr, nullptr);

        add_ln<<<MR, 128>>>(h, tmp, ln2_s + l * DM, ln2_b + l * DM);
    }

    // cls = h @ cls_w^T + b (A converted; output unrounded)
    gemm_tf32<1><<<dim3(1, 32, 1), 256, GEMM_SMEM>>>(
        h, DM, 0, 0, wb + W_CLS, DM, 0, 0, cls_b, cls, NCLS, 0, 0, MR, NCLS, DM, 0, 0,
        nullptr, nullptr, nullptr, nullptr);

    transpose_cls<<<dim3(TTT / 32, NCLS / 32, BB), dim3(32, 8)>>>(cls, outp);
}

// round 10
// speedup vs baseline: 1.5880x; 1.4242x over previous
#include <cuda_runtime.h>
#include <cuda_fp16.h>

// ---------------- problem constants ----------------
#define BB   2
#define TTT  2048
#define DM   512
#define NHD  8
#define DHD  64
#define NLAY 4
#define DI   2048
#define CIN  2048
#define NCLS 64
#define MR   (BB * TTT)   // 4096 token rows

// ---------------- scratch (device globals; no allocation allowed) ----------------
__device__ float g_h[(size_t)MR * DM];                 // fp32 residual stream
__device__ float g_tmp[(size_t)MR * DM];
__device__ float g_Bx[(size_t)BB * NHD * TTT * TTT];   // SHIFTED position scores (fp32)
__device__ float g_cls[(size_t)MR * NCLS];
// fp16 tensors
__device__ __half g_x16[(size_t)MR * CIN];
__device__ __half g_h16[(size_t)MR * DM];
__device__ __half g_heads16[(size_t)MR * 3 * DM];      // only K block (cols 512..1023) consumed
__device__ __half g_qw16[(size_t)MR * DM];
__device__ __half g_qr16[(size_t)MR * DM];
__device__ __half g_rk16[(size_t)TTT * DM];
__device__ __half g_pos16[(size_t)TTT * DM];
__device__ __half g_ff16[(size_t)MR * DI];
__device__ __half g_av16[(size_t)MR * DM];
__device__ __half g_vT16[(size_t)DM * BB * TTT];       // [d(512)][b(2)*T] transposed V
// fp16 weights: emb | qkv | rproj | o | ff1 | ff2 | cls
#define W_EMB  0
#define W_QKV  (W_EMB + DM * CIN)
#define W_RPJ  (W_QKV + NLAY * 3 * DM * DM)
#define W_O    (W_RPJ + NLAY * DM * DM)
#define W_FF1  (W_O + NLAY * DM * DM)
#define W_FF2  (W_FF1 + NLAY * DI * DM)
#define W_CLS  (W_FF2 + NLAY * DM * DI)
#define W_END  (W_CLS + NCLS * DM)
__device__ __half g_w16[(size_t)W_END];

// ---------------- helpers ----------------
__device__ __forceinline__ unsigned packh2(float a, float b) {
    __half2 h = __floats2half2_rn(a, b);
    return *(unsigned*)&h;
}

__device__ __forceinline__ void mma_f16(float* c, unsigned a0, unsigned a1,
                                        unsigned a2, unsigned a3,
                                        unsigned b0, unsigned b1) {
    asm volatile(
        "mma.sync.aligned.m16n8k16.row.col.f32.f16.f16.f32 "
        "{%0,%1,%2,%3}, {%4,%5,%6,%7}, {%8,%9}, {%0,%1,%2,%3};"
        : "+f"(c[0]), "+f"(c[1]), "+f"(c[2]), "+f"(c[3])
        : "r"(a0), "r"(a1), "r"(a2), "r"(a3), "r"(b0), "r"(b1));
}

__device__ __forceinline__ void cp16(void* dst, const void* src, int srcbytes) {
    unsigned u = (unsigned)__cvta_generic_to_shared(dst);
    asm volatile("cp.async.cg.shared.global [%0], [%1], 16, %2;"
                 :: "r"(u), "l"(src), "r"(srcbytes));
}
__device__ __forceinline__ void cp_commit() {
    asm volatile("cp.async.commit_group;");
}

// ---------------- fp32 -> fp16 weight conversion ----------------
__global__ void __launch_bounds__(256) round_copy16(const float* __restrict__ src,
                                                    __half* __restrict__ dst, int n)
{
    int i = (blockIdx.x * 256 + threadIdx.x) * 4;
    if (i < n) {
        float4 v = *(const float4*)(src + i);
        uint2 o;
        o.x = packh2(v.x, v.y);
        o.y = packh2(v.z, v.w);
        *(uint2*)(dst + i) = o;
    }
}

// ---------------- FP16 tensor-core GEMM, 2-stage cp.async, 2 CTAs/SM ----------------
// C[M,N] = A[M,K] @ B[N,K]^T (+fp32 bias)(+relu). Paired-k16 fragments, stride 48 halves.
#define G16_STG (128 * 48)                 // halves per stage per matrix
#define GEMM16_SMEM (4 * G16_STG * 2)      // 49152 B

__global__ void __launch_bounds__(256, 2) gemm16(
    const __half* __restrict__ A, int lda,
    const __half* __restrict__ B, int ldb,
    const float* __restrict__ bias,
    float* __restrict__ C, int ldc,
    __half* __restrict__ C16, int ldc16,
    int M, int N, int K, int relu,
    const float* __restrict__ rwb, const float* __restrict__ rrb,
    __half* __restrict__ qwO, __half* __restrict__ qrO,
    __half* __restrict__ vTO)
{
    extern __shared__ __half gs16[];
    __half* AsBase = gs16;
    __half* BsBase = gs16 + 2 * G16_STG;

    const int tid = threadIdx.x;
    const int warp = tid >> 5, lane = tid & 31;
    const int wm = warp >> 2, wn = warp & 3;
    const int g = lane >> 2, tg = lane & 3;
    const int m0 = blockIdx.y * 128, n0 = blockIdx.x * 128;

    float acc[4][4][4];
#pragma unroll
    for (int mt = 0; mt < 4; mt++)
#pragma unroll
        for (int nt = 0; nt < 4; nt++)
#pragma unroll
            for (int i = 0; i < 4; i++) acc[mt][nt][i] = 0.f;

    const int KT = K >> 5;

    auto load_stage = [&](int st, int k0) {
#pragma unroll
        for (int i = 0; i < 2; i++) {
            int idx = tid + i * 256;        // 0..511
            int row = idx >> 2;
            int kq = (idx & 3) * 8;         // half offset
            cp16(AsBase + st * G16_STG + row * 48 + kq,
                 A + (size_t)(m0 + row) * lda + k0 + kq, 16);
        }
#pragma unroll
        for (int i = 0; i < 2; i++) {
            int idx = tid + i * 256;
            int row = idx >> 2;
            int kq = (idx & 3) * 8;
            int ok = (n0 + row) < N;
            cp16(BsBase + st * G16_STG + row * 48 + kq,
                 B + (size_t)(ok ? (n0 + row) : 0) * ldb + k0 + kq, ok ? 16 : 0);
        }
        cp_commit();
    };

    load_stage(0, 0);

    for (int kt = 0; kt < KT; kt++) {
        const int st = kt & 1;
        if (kt + 1 < KT) {
            load_stage(st ^ 1, (kt + 1) * 32);
            asm volatile("cp.async.wait_group 1;");
        } else {
            asm volatile("cp.async.wait_group 0;");
        }
        __syncthreads();

        const __half* Asl = AsBase + st * G16_STG;
        const __half* Bsl = BsBase + st * G16_STG;

#pragma unroll
        for (int ks = 0; ks < 2; ks++) {
            const int kk = ks * 16 + 4 * tg;
            uint2 ua[4][2];
            uint2 vb[4];
#pragma unroll
            for (int mt = 0; mt < 4; mt++) {
                int r = wm * 64 + mt * 16;
                ua[mt][0] = *(const uint2*)(Asl + (r + g) * 48 + kk);
                ua[mt][1] = *(const uint2*)(Asl + (r + g + 8) * 48 + kk);
            }
#pragma unroll
            for (int nt = 0; nt < 4; nt++) {
                int c = wn * 32 + nt * 8;
                vb[nt] = *(const uint2*)(Bsl + (c + g) * 48 + kk);
            }
#pragma unroll
            for (int mt = 0; mt < 4; mt++)
#pragma unroll
                for (int nt = 0; nt < 4; nt++)
                    mma_f16(acc[mt][nt], ua[mt][0].x, ua[mt][1].x,
                            ua[mt][0].y, ua[mt][1].y, vb[nt].x, vb[nt].y);
        }
        __syncthreads();
    }

#pragma unroll
    for (int mt = 0; mt < 4; mt++) {
        int r0 = m0 + wm * 64 + mt * 16 + g;
#pragma unroll
        for (int nt = 0; nt < 4; nt++) {
            int c0 = n0 + wn * 32 + nt * 8 + tg * 2;
            if (c0 < N) {
                float b0v = bias ? bias[c0] : 0.f;
                float b1v = bias ? bias[c0 + 1] : 0.f;
                float v0 = acc[mt][nt][0] + b0v;
                float v1 = acc[mt][nt][1] + b1v;
                float v2 = acc[mt][nt][2] + b0v;
                float v3 = acc[mt][nt][3] + b1v;
                if (relu) {
                    v0 = fmaxf(v0, 0.f); v1 = fmaxf(v1, 0.f);
                    v2 = fmaxf(v2, 0.f); v3 = fmaxf(v3, 0.f);
                }
                if (C) {
                    *(float2*)(C + (size_t)r0 * ldc + c0) = make_float2(v0, v1);
                    *(float2*)(C + (size_t)(r0 + 8) * ldc + c0) = make_float2(v2, v3);
                }
                if (C16) {
                    *(unsigned*)(C16 + (size_t)r0 * ldc16 + c0) = packh2(v0, v1);
                    *(unsigned*)(C16 + (size_t)(r0 + 8) * ldc16 + c0) = packh2(v2, v3);
                }
                if (qwO && c0 < DM) {
                    float w0 = rwb[c0], w1 = rwb[c0 + 1];
                    float r0b = rrb[c0], r1b = rrb[c0 + 1];
                    *(unsigned*)(qwO + (size_t)r0 * DM + c0) = packh2(v0 + w0, v1 + w1);
                    *(unsigned*)(qwO + (size_t)(r0 + 8) * DM + c0) = packh2(v2 + w0, v3 + w1);
                    *(unsigned*)(qrO + (size_t)r0 * DM + c0) = packh2(v0 + r0b, v1 + r1b);
                    *(unsigned*)(qrO + (size_t)(r0 + 8) * DM + c0) = packh2(v2 + r0b, v3 + r1b);
                }
                if (vTO && c0 >= 2 * DM) {
                    int d = c0 - 2 * DM;
                    int bb_ = r0 >> 11, t0 = r0 & 2047;
                    __half* vp0 = vTO + (size_t)d * (BB * TTT) + bb_ * TTT;
                    __half* vp1 = vTO + (size_t)(d + 1) * (BB * TTT) + bb_ * TTT;
                    vp0[t0] = __float2half(v0);
                    vp1[t0] = __float2half(v1);
                    vp0[t0 + 8] = __float2half(v2);
                    vp1[t0 + 8] = __float2half(v3);
                }
            }
        }
    }
}

// ---------------- BD GEMM (fp16 core) with shifted-scatter fp32 epilogue ----------------
__device__ __forceinline__ void bd_store(float* __restrict__ BDs, int i, int c, float v) {
    int thr = TTT - 1 - i;
    if (c >= thr)      BDs[(size_t)i * TTT + (c - thr)] = v;
    else if (i > 0)    BDs[(size_t)(i - 1) * TTT + (c + i + 1)] = v;
}

__global__ void __launch_bounds__(256, 2) gemm_bd16(
    const __half* __restrict__ A,   // qr16 [MR][512]
    const __half* __restrict__ B,   // rk16 [T][512]
    float* __restrict__ C)          // BDs [16][T][T]
{
    const int z = blockIdx.z, zb = z >> 3, zn = z & 7;
    A += (size_t)zb * TTT * DM + zn * 64;
    B += zn * 64;
    C += (size_t)z * TTT * TTT;

    extern __shared__ __half gs16[];
    __half* AsBase = gs16;
    __half* BsBase = gs16 + 2 * G16_STG;

    const int tid = threadIdx.x;
    const int warp = tid >> 5, lane = tid & 31;
    const int wm = warp >> 2, wn = warp & 3;
    const int g = lane >> 2, tg = lane & 3;
    const int m0 = blockIdx.y * 128, n0 = blockIdx.x * 128;

    float acc[4][4][4];
#pragma unroll
    for (int mt = 0; mt < 4; mt++)
#pragma unroll
        for (int nt = 0; nt < 4; nt++)
#pragma unroll
            for (int i = 0; i < 4; i++) acc[mt][nt][i] = 0.f;

    auto load_stage = [&](int st, int k0) {
#pragma unroll
        for (int i = 0; i < 2; i++) {
            int idx = tid + i * 256;
            int row = idx >> 2;
            int kq = (idx & 3) * 8;
            cp16(AsBase + st * G16_STG + row * 48 + kq,
                 A + (size_t)(m0 + row) * DM + k0 + kq, 16);
        }
#pragma unroll
        for (int i = 0; i < 2; i++) {
            int idx = tid + i * 256;
            int row = idx >> 2;
            int kq = (idx & 3) * 8;
            cp16(BsBase + st * G16_STG + row * 48 + kq,
                 B + (size_t)(n0 + row) * DM + k0 + kq, 16);
        }
        cp_commit();
    };

    load_stage(0, 0);

#pragma unroll
    for (int kt = 0; kt < 2; kt++) {
        const int st = kt & 1;
        if (kt == 0) {
            load_stage(1, 32);
            asm volatile("cp.async.wait_group 1;");
        } else {
            asm volatile("cp.async.wait_group 0;");
        }
        __syncthreads();

        const __half* Asl = AsBase + st * G16_STG;
        const __half* Bsl = BsBase + st * G16_STG;

#pragma unroll
        for (int ks = 0; ks < 2; ks++) {
            const int kk = ks * 16 + 4 * tg;
            uint2 ua[4][2];
            uint2 vb[4];
#pragma unroll
            for (int mt = 0; mt < 4; mt++) {
                int r = wm * 64 + mt * 16;
                ua[mt][0] = *(const uint2*)(Asl + (r + g) * 48 + kk);
                ua[mt][1] = *(const uint2*)(Asl + (r + g + 8) * 48 + kk);
            }
#pragma unroll
            for (int nt = 0; nt < 4; nt++) {
                int c = wn * 32 + nt * 8;
                vb[nt] = *(const uint2*)(Bsl + (c + g) * 48 + kk);
            }
#pragma unroll
            for (int mt = 0; mt < 4; mt++)
#pragma unroll
                for (int nt = 0; nt < 4; nt++)
                    mma_f16(acc[mt][nt], ua[mt][0].x, ua[mt][1].x,
                            ua[mt][0].y, ua[mt][1].y, vb[nt].x, vb[nt].y);
        }
        __syncthreads();
    }

#pragma unroll
    for (int mt = 0; mt < 4; mt++) {
        int i0r = m0 + wm * 64 + mt * 16 + g;
        int i1r = i0r + 8;
#pragma unroll
        for (int nt = 0; nt < 4; nt++) {
            int c0 = n0 + wn * 32 + nt * 8 + tg * 2;
            bd_store(C, i0r, c0,     acc[mt][nt][0]);
            bd_store(C, i0r, c0 + 1, acc[mt][nt][1]);
            bd_store(C, i1r, c0,     acc[mt][nt][2]);
            bd_store(C, i1r, c0 + 1, acc[mt][nt][3]);
        }
    }
}

// ---------------- fused fp16 flash attention, 2 CTAs/SM ----------------
// smem halves: sP [128][80] | sK [2][64][80] | sVt [2][64][80]
#define FP_ELEMS (128 * 80)
#define FK_ELEMS (64 * 80)
#define FA16_SMEM ((FP_ELEMS + 4 * FK_ELEMS) * 2)   // 61440 B

__global__ void __launch_bounds__(256, 2) flash16(
    const __half* __restrict__ qw,    // [MR][512]
    const __half* __restrict__ hK,    // heads16 [MR][1536], K at +512
    const __half* __restrict__ vT,    // [512][BB*T]
    const float* __restrict__ BDs,    // [16][T][T] pre-shifted
    __half* __restrict__ av,          // [MR][512]
    float scale)
{
    extern __shared__ __half fsm[];
    __half* sP = fsm;                       // [128][80]
    __half* sK = fsm + FP_ELEMS;            // [2][64][80]
    __half* sV = sK + 2 * FK_ELEMS;         // [2][64][80] (rows = d, cols = j)

    const int tid = threadIdx.x;
    const int w = tid >> 5, lane = tid & 31;
    const int g = lane >> 2, tg = lane & 3;
    const int i0 = blockIdx.x * 128;
    const int bn = blockIdx.y;
    const int b = bn >> 3, n = bn & 7;

    const __half* Qb = qw + (size_t)(b * TTT) * DM + n * 64;
    const __half* Kb = hK + (size_t)(b * TTT) * (3 * DM) + DM + n * 64;
    const __half* Vb = vT + (size_t)(n * 64) * (BB * TTT) + b * TTT;
    const float* Bb = BDs + (size_t)bn * TTT * TTT;

    auto kv_load = [&](int st, int j0) {
#pragma unroll
        for (int it = 0; it < 2; it++) {
            int idx = tid + it * 256;       // 0..511
            int row = idx >> 3, c8 = (idx & 7) * 8;
            cp16(sK + st * FK_ELEMS + row * 80 + c8,
                 Kb + (size_t)(j0 + row) * (3 * DM) + c8, 16);
        }
#pragma unroll
        for (int it = 0; it < 2; it++) {
            int idx = tid + it * 256;
            int row = idx >> 3, c8 = (idx & 7) * 8;
            cp16(sV + st * FK_ELEMS + row * 80 + c8,
                 Vb + (size_t)row * (BB * TTT) + j0 + c8, 16);
        }
        cp_commit();
    };

    kv_load(0, 0);

    // stage Q
#pragma unroll
    for (int it = 0; it < 4; it++) {
        int idx = tid + it * 256;           // 1024 uint4 slots
        int row = idx >> 3, h8 = (idx & 7) * 8;
        uint4 v = *(const uint4*)(Qb + (size_t)(i0 + row) * DM + h8);
        *(uint4*)(sP + row * 80 + h8) = v;
    }
    __syncthreads();

    const int r0 = 16 * w + g;
    const int iR0 = i0 + r0, iR1 = iR0 + 8;
    const float* BDr0 = Bb + (size_t)iR0 * TTT;
    const float* BDr1 = Bb + (size_t)iR1 * TTT;

    uint2 qa[4][2];
#pragma unroll
    for (int kf = 0; kf < 4; kf++) {
        qa[kf][0] = *(const uint2*)(sP + r0 * 80 + kf * 16 + 4 * tg);
        qa[kf][1] = *(const uint2*)(sP + (r0 + 8) * 80 + kf * 16 + 4 * tg);
    }

    float Oacc[8][4];
#pragma unroll
    for (int nf = 0; nf < 8; nf++)
#pragma unroll
        for (int i = 0; i < 4; i++) Oacc[nf][i] = 0.f;
    float mr0 = -1e30f, mr1 = -1e30f, lr0 = 0.f, lr1 = 0.f;

    for (int jt = 0; jt < TTT / 64; jt++) {
        const int st = jt & 1;
        const int j0 = jt * 64;
        if (jt + 1 < TTT / 64) {
            kv_load(st ^ 1, (jt + 1) * 64);
            asm volatile("cp.async.wait_group 1;");
        } else {
            asm volatile("cp.async.wait_group 0;");
        }
        __syncthreads();

        const __half* Ks = sK + st * FK_ELEMS;
        const __half* Vs = sV + st * FK_ELEMS;

        // ---- S = Q @ K^T
        float s[8][4];
#pragma unroll
        for (int nf = 0; nf < 8; nf++)
#pragma unroll
            for (int i = 0; i < 4; i++) s[nf][i] = 0.f;
#pragma unroll
        for (int kf = 0; kf < 4; kf++) {
            const int kk = kf * 16 + 4 * tg;
#pragma unroll
            for (int nf = 0; nf < 8; nf++) {
                uint2 vb = *(const uint2*)(Ks + (nf * 8 + g) * 80 + kk);
                mma_f16(s[nf], qa[kf][0].x, qa[kf][1].x, qa[kf][0].y, qa[kf][1].y,
                        vb.x, vb.y);
            }
        }

        // ---- add shifted BD (zero slot j == i+1), scale
#pragma unroll
        for (int nf = 0; nf < 8; nf++) {
            int j = j0 + nf * 8 + 2 * tg;
            float2 y0 = *(const float2*)(BDr0 + j);
            float2 y1 = *(const float2*)(BDr1 + j);
            float b00 = (j     == iR0 + 1) ? 0.f : y0.x;
            float b01 = (j + 1 == iR0 + 1) ? 0.f : y0.y;
            float b10 = (j     == iR1 + 1) ? 0.f : y1.x;
            float b11 = (j + 1 == iR1 + 1) ? 0.f : y1.y;
            s[nf][0] = (s[nf][0] + b00) * scale;
            s[nf][1] = (s[nf][1] + b01) * scale;
            s[nf][2] = (s[nf][2] + b10) * scale;
            s[nf][3] = (s[nf][3] + b11) * scale;
        }

        // ---- online softmax
        float m0 = -1e30f, m1 = -1e30f;
#pragma unroll
        for (int nf = 0; nf < 8; nf++) {
            m0 = fmaxf(m0, fmaxf(s[nf][0], s[nf][1]));
            m1 = fmaxf(m1, fmaxf(s[nf][2], s[nf][3]));
        }
        m0 = fmaxf(m0, __shfl_xor_sync(0xffffffffu, m0, 1));
        m0 = fmaxf(m0, __shfl_xor_sync(0xffffffffu, m0, 2));
        m1 = fmaxf(m1, __shfl_xor_sync(0xffffffffu, m1, 1));
        m1 = fmaxf(m1, __shfl_xor_sync(0xffffffffu, m1, 2));
        float mn0 = fmaxf(mr0, m0), mn1 = fmaxf(mr1, m1);
        float a0 = __expf(mr0 - mn0), a1 = __expf(mr1 - mn1);

        float l0 = 0.f, l1 = 0.f;
#pragma unroll
        for (int nf = 0; nf < 8; nf++) {
            float p0 = __expf(s[nf][0] - mn0);
            float p1 = __expf(s[nf][1] - mn0);
            float p2 = __expf(s[nf][2] - mn1);
            float p3 = __expf(s[nf][3] - mn1);
            l0 += p0 + p1; l1 += p2 + p3;
            int c = nf * 8 + 2 * tg;
            *(unsigned*)(sP + r0 * 80 + c)       = packh2(p0, p1);
            *(unsigned*)(sP + (r0 + 8) * 80 + c) = packh2(p2, p3);
        }
        l0 += __shfl_xor_sync(0xffffffffu, l0, 1);
        l0 += __shfl_xor_sync(0xffffffffu, l0, 2);
        l1 += __shfl_xor_sync(0xffffffffu, l1, 1);
        l1 += __shfl_xor_sync(0xffffffffu, l1, 2);
        lr0 = lr0 * a0 + l0;
        lr1 = lr1 * a1 + l1;
        mr0 = mn0; mr1 = mn1;
#pragma unroll
        for (int nf = 0; nf < 8; nf++) {
            Oacc[nf][0] *= a0; Oacc[nf][1] *= a0;
            Oacc[nf][2] *= a1; Oacc[nf][3] *= a1;
        }
        __syncwarp();

        // ---- O += P @ V   (A from sP rows, B from Vs rows=d, k=j contiguous)
#pragma unroll
        for (int kf = 0; kf < 4; kf++) {
            const int kk = kf * 16 + 4 * tg;
            uint2 pa0 = *(const uint2*)(sP + r0 * 80 + kk);
            uint2 pa1 = *(const uint2*)(sP + (r0 + 8) * 80 + kk);
#pragma unroll
            for (int nf = 0; nf < 8; nf++) {
                uint2 vb = *(const uint2*)(Vs + (nf * 8 + g) * 80 + kk);
                mma_f16(Oacc[nf], pa0.x, pa1.x, pa0.y, pa1.y, vb.x, vb.y);
            }
        }
        __syncthreads();
    }

    float inv0 = 1.f / lr0, inv1 = 1.f / lr1;
#pragma unroll
    for (int nf = 0; nf < 8; nf++) {
        int col = n * 64 + nf * 8 + 2 * tg;
        *(unsigned*)(av + (size_t)(b * TTT + iR0) * DM + col) =
            packh2(Oacc[nf][0] * inv0, Oacc[nf][1] * inv0);
        *(unsigned*)(av + (size_t)(b * TTT + iR1) * DM + col) =
            packh2(Oacc[nf][2] * inv1, Oacc[nf][3] * inv1);
    }
}

// ---------------- residual add + LayerNorm (fp32 stream + fp16 mirror) ----------------
__global__ void __launch_bounds__(128) add_ln(
    float* __restrict__ h, __half* __restrict__ h16, const float* __restrict__ a,
    const float* __restrict__ gs, const float* __restrict__ gb)
{
    const int row = blockIdx.x, tid = threadIdx.x;
    float* hp = h + (size_t)row * DM;
    __half* hp16 = h16 + (size_t)row * DM;
    const float* ap = a + (size_t)row * DM;
    float v[4];
    float s = 0.f;
#pragma unroll
    for (int j = 0; j < 4; j++) { int c = tid + j * 128; v[j] = hp[c] + ap[c]; s += v[j]; }

    __shared__ float red[8];
#pragma unroll
    for (int o = 16; o > 0; o >>= 1) s += __shfl_xor_sync(0xffffffffu, s, o);
    if ((tid & 31) == 0) red[tid >> 5] = s;
    __syncthreads();
    float mean = (red[0] + red[1] + red[2] + red[3]) * (1.f / 512.f);

    float var = 0.f;
#pragma unroll
    for (int j = 0; j < 4; j++) { float d = v[j] - mean; var += d * d; }
#pragma unroll
    for (int o = 16; o > 0; o >>= 1) var += __shfl_xor_sync(0xffffffffu, var, o);
    if ((tid & 31) == 0) red[4 + (tid >> 5)] = var;
    __syncthreads();
    var = (red[4] + red[5] + red[6] + red[7]) * (1.f / 512.f);
    float rs = rsqrtf(var + 1e-5f);
#pragma unroll
    for (int j = 0; j < 4; j++) {
        int c = tid + j * 128;
        float o = (v[j] - mean) * rs * gs[c] + gb[c];
        hp[c] = o;
        hp16[c] = __float2half(o);
    }
}

// ---------------- small helpers ----------------
__global__ void __launch_bounds__(256) pos_kernel16(__half* __restrict__ pos)
{
    int p = blockIdx.x;
    int f = threadIdx.x;
    float ps = (float)(TTT - 1 - p);
    float invf = 1.0f / powf(10000.0f, (float)(2 * f) / (float)DM);
    float ang = ps * invf;
    pos[(size_t)p * DM + f]       = __float2half(sinf(ang));
    pos[(size_t)p * DM + 256 + f] = __float2half(cosf(ang));
}

__global__ void transpose_x16(const float* __restrict__ x, __half* __restrict__ xT)
{
    __shared__ float tile[32][33];
    int b = blockIdx.z;
    int t0 = blockIdx.x * 32, c0 = blockIdx.y * 32;
    int tx = threadIdx.x, ty = threadIdx.y;
#pragma unroll
    for (int i = 0; i < 4; i++) {
        int c = c0 + ty + i * 8;
        tile[ty + i * 8][tx] = x[((size_t)b * CIN + c) * TTT + t0 + tx];
    }
    __syncthreads();
#pragma unroll
    for (int i = 0; i < 4; i++) {
        int t = t0 + ty + i * 8;
        xT[((size_t)b * TTT + t) * CIN + c0 + tx] = __float2half(tile[tx][ty + i * 8]);
    }
}

__global__ void transpose_cls(const float* __restrict__ tmp, float* __restrict__ outp)
{
    __shared__ float tile[32][33];
    int b = blockIdx.z;
    int t0 = blockIdx.x * 32, k0 = blockIdx.y * 32;
    int tx = threadIdx.x, ty = threadIdx.y;
#pragma unroll
    for (int i = 0; i < 4; i++) {
        int t = t0 + ty + i * 8;
        tile[ty + i * 8][tx] = tmp[((size_t)b * TTT + t) * NCLS + k0 + tx];
    }
    __syncthreads();
#pragma unroll
    for (int i = 0; i < 4; i++) {
        int k = k0 + ty + i * 8;
        outp[((size_t)b * NCLS + k) * TTT + t0 + tx] = tile[tx][ty + i * 8];
    }
}

// ---------------- host orchestration ----------------
extern "C" void kernel_launch(void* const* d_in, const int* in_sizes, int n_in,
                              void* d_out, int out_size)
{
    const float* x        = (const float*)d_in[0];
    const float* emb_w    = (const float*)d_in[1];
    const float* emb_b    = (const float*)d_in[2];
    const float* r_w_bias = (const float*)d_in[3];
    const float* r_r_bias = (const float*)d_in[4];
    const float* qkv_w    = (const float*)d_in[5];
    const float* qkv_b    = (const float*)d_in[6];
    const float* r_proj_w = (const float*)d_in[7];
    const float* o_w      = (const float*)d_in[8];
    const float* ln1_s    = (const float*)d_in[9];
    const float* ln1_b    = (const float*)d_in[10];
    const float* ff1_w    = (const float*)d_in[11];
    const float* ff1_b    = (const float*)d_in[12];
    const float* ff2_w    = (const float*)d_in[13];
    const float* ff2_b    = (const float*)d_in[14];
    const float* ln2_s    = (const float*)d_in[15];
    const float* ln2_b    = (const float*)d_in[16];
    const float* cls_w    = (const float*)d_in[17];
    const float* cls_b    = (const float*)d_in[18];
    float* outp = (float*)d_out;

    float *h, *tmp, *Bx, *cls;
    __half *x16, *h16, *heads16, *qw16, *qr16, *rk16, *pos16, *ff16, *av16, *vT16, *w16;
    cudaGetSymbolAddress((void**)&h, g_h);
    cudaGetSymbolAddress((void**)&tmp, g_tmp);
    cudaGetSymbolAddress((void**)&Bx, g_Bx);
    cudaGetSymbolAddress((void**)&cls, g_cls);
    cudaGetSymbolAddress((void**)&x16, g_x16);
    cudaGetSymbolAddress((void**)&h16, g_h16);
    cudaGetSymbolAddress((void**)&heads16, g_heads16);
    cudaGetSymbolAddress((void**)&qw16, g_qw16);
    cudaGetSymbolAddress((void**)&qr16, g_qr16);
    cudaGetSymbolAddress((void**)&rk16, g_rk16);
    cudaGetSymbolAddress((void**)&pos16, g_pos16);
    cudaGetSymbolAddress((void**)&ff16, g_ff16);
    cudaGetSymbolAddress((void**)&av16, g_av16);
    cudaGetSymbolAddress((void**)&vT16, g_vT16);
    cudaGetSymbolAddress((void**)&w16, g_w16);

    cudaFuncSetAttribute(gemm16, cudaFuncAttributeMaxDynamicSharedMemorySize, GEMM16_SMEM);
    cudaFuncSetAttribute(gemm_bd16, cudaFuncAttributeMaxDynamicSharedMemorySize, GEMM16_SMEM);
    cudaFuncSetAttribute(flash16, cudaFuncAttributeMaxDynamicSharedMemorySize, FA16_SMEM);

    const float scale = 1.0f / 8.0f;

    // weights -> fp16
    auto rc = [&](const float* src, __half* dst, int n) {
        round_copy16<<<(n / 4 + 255) / 256, 256>>>(src, dst, n);
    };
    rc(emb_w,    w16 + W_EMB, DM * CIN);
    rc(qkv_w,    w16 + W_QKV, NLAY * 3 * DM * DM);
    rc(r_proj_w, w16 + W_RPJ, NLAY * DM * DM);
    rc(o_w,      w16 + W_O,   NLAY * DM * DM);
    rc(ff1_w,    w16 + W_FF1, NLAY * DI * DM);
    rc(ff2_w,    w16 + W_FF2, NLAY * DM * DI);
    rc(cls_w,    w16 + W_CLS, NCLS * DM);

    transpose_x16<<<dim3(TTT / 32, CIN / 32, BB), dim3(32, 8)>>>(x, x16);
    pos_kernel16<<<TTT, 256>>>(pos16);

    // embed: h(+h16) = x16 @ emb_w^T + emb_b
    gemm16<<<dim3(4, 32), 256, GEMM16_SMEM>>>(
        x16, CIN, w16 + W_EMB, CIN, emb_b, h, DM, h16, DM, MR, DM, CIN, 0,
        nullptr, nullptr, nullptr, nullptr, nullptr);

    for (int l = 0; l < NLAY; l++) {
        const __half* qkvW = w16 + W_QKV + (size_t)l * 3 * DM * DM;
        const float*  qkvB = qkv_b + (size_t)l * 3 * DM;
        const __half* rW   = w16 + W_RPJ + (size_t)l * DM * DM;
        const __half* oW   = w16 + W_O + (size_t)l * DM * DM;
        const __half* f1W  = w16 + W_FF1 + (size_t)l * DI * DM;
        const float*  f1B  = ff1_b + (size_t)l * DI;
        const __half* f2W  = w16 + W_FF2 + (size_t)l * DM * DI;
        const float*  f2B  = ff2_b + (size_t)l * DM;

        // qkv: heads16 (K), qw16/qr16 (Q+biases), vT16 (V transposed)
        gemm16<<<dim3(12, 32), 256, GEMM16_SMEM>>>(
            h16, DM, qkvW, DM, qkvB, nullptr, 0, heads16, 3 * DM, MR, 3 * DM, DM, 0,
            r_w_bias, r_r_bias, qw16, qr16, vT16);

        // rk16 = pos16 @ r_proj_w^T
        gemm16<<<dim3(4, 16), 256, GEMM16_SMEM>>>(
            pos16, DM, rW, DM, nullptr, nullptr, 0, rk16, DM, TTT, DM, DM, 0,
            nullptr, nullptr, nullptr, nullptr, nullptr);

        // BDs = rel_shift(qr @ rk^T) scatter-stored
        gemm_bd16<<<dim3(16, 16, BB * NHD), 256, GEMM16_SMEM>>>(qr16, rk16, Bx);

        // fused attention
        flash16<<<dim3(TTT / 128, BB * NHD), 256, FA16_SMEM>>>(
            qw16, heads16, vT16, Bx, av16, scale);

        // attn_out = av16 @ o_w^T -> tmp fp32
        gemm16<<<dim3(4, 32), 256, GEMM16_SMEM>>>(
            av16, DM, oW, DM, nullptr, tmp, DM, nullptr, 0, MR, DM, DM, 0,
            nullptr, nullptr, nullptr, nullptr, nullptr);

        add_ln<<<MR, 128>>>(h, h16, tmp, ln1_s + l * DM, ln1_b + l * DM);

        // ff16 = relu(h16 @ ff1^T + b)
        gemm16<<<dim3(16, 32), 256, GEMM16_SMEM>>>(
            h16, DM, f1W, DM, f1B, nullptr, 0, ff16, DI, MR, DI, DM, 1,
            nullptr, nullptr, nullptr, nullptr, nullptr);

        // tmp = ff16 @ ff2^T + b
        gemm16<<<dim3(4, 32), 256, GEMM16_SMEM>>>(
            ff16, DI, f2W, DI, f2B, tmp, DM, nullptr, 0, MR, DM, DI, 0,
            nullptr, nullptr, nullptr, nullptr, nullptr);

        add_ln<<<MR, 128>>>(h, h16, tmp, ln2_s + l * DM, ln2_b + l * DM);
    }

    // cls = h16 @ cls_w^T + b
    gemm16<<<dim3(1, 32), 256, GEMM16_SMEM>>>(
        h16, DM, w16 + W_CLS, DM, cls_b, cls, NCLS, nullptr, 0, MR, NCLS, DM, 0,
        nullptr, nullptr, nullptr, nullptr, nullptr);

    transpose_cls<<<dim3(TTT / 32, NCLS / 32, BB), dim3(32, 8)>>>(cls, outp);
}